// round 10
// baseline (speedup 1.0000x reference)
#include <cuda_runtime.h>
#include <cstdint>

#define B_ 4
#define N_ 8192
#define C_ 64
#define K_ 16
#define O_ 128

#define CTILE 64                   // candidates per tile
#define NT (N_ / CTILE)            // 128 tiles
#define M_KEEP 24                  // filter margin (>=16)
#define QS 20.0f                   // int8 quantization scale
#define NL 2                       // partial lists per query (column halves)

// ---------------- scratch (no allocs allowed) ----------------
__device__ __align__(16) float    g_feats[B_ * N_ * C_];
__device__ __align__(16) float    g_xx[B_ * N_];
__device__ __align__(16) unsigned g_q8T[B_ * 16 * N_];    // int8 feats, k4-plane major
__device__ __align__(16) int      g_xxq[B_ * N_];         // quantized sq norms
__device__ __align__(16) int      g_knn[B_ * N_ * K_];
__device__ __align__(16) float    g_pval[B_ * NL * N_ * M_KEEP];
__device__ __align__(16) int      g_pidx[B_ * NL * N_ * M_KEEP];

typedef unsigned long long u64;

// ---------------- packed f32x2 helpers (sm_103a) ----------------
__device__ __forceinline__ u64 fma2(u64 a, u64 b, u64 c) {
    u64 d;
    asm("fma.rn.f32x2 %0, %1, %2, %3;" : "=l"(d) : "l"(a), "l"(b), "l"(c));
    return d;
}
__device__ __forceinline__ u64 add2(u64 a, u64 b) {
    u64 d;
    asm("add.rn.f32x2 %0, %1, %2;" : "=l"(d) : "l"(a), "l"(b));
    return d;
}
__device__ __forceinline__ float psum(u64 v) {
    return __uint_as_float((unsigned)v) + __uint_as_float((unsigned)(v >> 32));
}
__device__ __forceinline__ int dp4a(int acc, unsigned a, unsigned b) {
    int d;
    asm("dp4a.s32.s32 %0, %1, %2, %3;" : "=r"(d) : "r"(a), "r"(b), "r"(acc));
    return d;
}
__device__ __forceinline__ uint32_t smem_u32(const void* p) {
    uint32_t a;
    asm("{ .reg .u64 t; cvta.to.shared.u64 t, %1; cvt.u32.u64 %0, t; }" : "=r"(a) : "l"(p));
    return a;
}
__device__ __forceinline__ void cp_async16(uint32_t dst, const void* src) {
    asm volatile("cp.async.cg.shared.global [%0], [%1], 16;" :: "r"(dst), "l"(src) : "memory");
}
__device__ __forceinline__ void cp_commit() {
    asm volatile("cp.async.commit_group;" ::: "memory");
}
__device__ __forceinline__ void cp_wait0() {
    asm volatile("cp.async.wait_group 0;" ::: "memory");
}

// ---------------- kernel 1: transpose, norms, int8 quantize (k4 planes) ----------------
__global__ void __launch_bounds__(256) prep_kernel(const float* __restrict__ x) {
    int idx = blockIdx.x * 256 + threadIdx.x;      // 0 .. B*N-1
    int b = idx >> 13;
    int n = idx & (N_ - 1);
    const float* xb = x + (size_t)b * C_ * N_ + n;
    float v[C_];
    float acc = 0.f;
#pragma unroll
    for (int c = 0; c < C_; ++c) {
        float t = xb[(size_t)c * N_];              // coalesced across threads
        v[c] = t;
        acc = fmaf(t, t, acc);
    }
    float4* fp = reinterpret_cast<float4*>(g_feats + (size_t)idx * C_);
#pragma unroll
    for (int i = 0; i < C_ / 4; ++i)
        fp[i] = make_float4(v[4 * i], v[4 * i + 1], v[4 * i + 2], v[4 * i + 3]);

    // int8 quantization, written as 16 k4-planes (coalesced per plane)
    int xxq = 0;
#pragma unroll
    for (int g = 0; g < 16; ++g) {
        unsigned p = 0;
#pragma unroll
        for (int e = 0; e < 4; ++e) {
            float s = fminf(fmaxf(v[4 * g + e] * QS, -127.f), 127.f);
            int qi = __float2int_rn(s);
            xxq += qi * qi;
            p |= ((unsigned)qi & 0xFFu) << (8 * e);
        }
        g_q8T[((size_t)b * 16 + g) * N_ + n] = p;
    }
    g_xxq[idx] = xxq;
    g_xx[idx] = acc;
}

// ---------------- kernel 2: register-tiled dp4a KNN filter + exact fp32 rescore ----------------
// Grid (64, B_), 256 threads, occ 2. CTA: 128 queries x all 8192 candidates.
// MMA thread (qi=t&15, ci=t>>4) owns 8 queries x 4 candidates.
// smem layout (bytes):
#define S_Q    0                          // Q planes [k4][128q] = 8192
#define S_X    8192                       // 2 x X planes [k4][64c] = 2 x 4096
#define S_DIST 16384                      // 128 x 64 ints (chunk-swizzled) = 32768
#define S_CXQ  49152                      // 2 x 64 ints
#define S_MV   49664                      // 256 x M_KEEP
#define S_MI   (S_MV + 256 * M_KEEP * 4)
#define KNN_SMEM (S_MI + 256 * M_KEEP * 4)   // 98816

__global__ void __launch_bounds__(256) knn_kernel() {
    extern __shared__ char smem[];
    uint32_t sb = smem_u32(smem);
    const int t = threadIdx.x;
    const int qi = t & 15;                 // MMA: query group (8 rows qi*8..)
    const int ci = t >> 4;                 // MMA: candidate group (4 cols ci*4..)
    const int b = blockIdx.y;
    const int q0 = blockIdx.x * 128;

    const unsigned* q8T = g_q8T + (size_t)b * 16 * N_;
    const int* xxqb = g_xxq + b * N_;

    int* s_cxq = reinterpret_cast<int*>(smem + S_CXQ);
    int* mvI = reinterpret_cast<int*>(smem + S_MV) + t * M_KEEP;
    int* mi  = reinterpret_cast<int*>(smem + S_MI) + t * M_KEEP;

    // ---- load Q tile planes: 16 planes x 512B = 512 chunks, 2 per thread ----
#pragma unroll
    for (int i = 0; i < 2; ++i) {
        int c = t + i * 256;
        int k4 = c >> 5, off = c & 31;
        cp_async16(sb + S_Q + (uint32_t)c * 16, q8T + (size_t)k4 * N_ + q0 + off * 4);
    }
    // ---- X tile loader: 16 planes x 256B = 256 chunks, 1 per thread ----
    auto issueX = [&](int tile, int buf) {
        int k4 = t >> 4, off = t & 15;
        cp_async16(sb + S_X + buf * 4096 + (uint32_t)t * 16,
                   q8T + (size_t)k4 * N_ + tile * CTILE + off * 4);
        cp_commit();
        if (t < CTILE) s_cxq[buf * CTILE + t] = xxqb[tile * CTILE + t];
    };
    issueX(0, 0);

    // per-thread query norms (8 MMA rows)
    int qn[8];
#pragma unroll
    for (int i = 0; i < 8; ++i) qn[i] = xxqb[q0 + qi * 8 + i];

    // scan thread mapping: srow = m*8 + w covers 0..127; shalf = column half
    const int m = t & 15;
    const int shalf = (t >> 4) & 1;
    const int w = t >> 5;
    const int srow = m * 8 + w;

#pragma unroll
    for (int i = 0; i < M_KEEP; ++i) { mvI[i] = 0x80000000; mi[i] = 0; }
    int thrI = 0x80000000;

    cp_wait0();
    __syncthreads();                         // Q + X[0] + cxq[0] visible

    for (int tile = 0; tile < NT; ++tile) {
        const int buf = tile & 1;
        if (tile + 1 < NT) issueX(tile + 1, buf ^ 1);

        // ---- MMA: 8x4 int tile over 16 k4-steps ----
        const uint4* Qp = reinterpret_cast<const uint4*>(smem + S_Q);
        const uint4* Xp = reinterpret_cast<const uint4*>(smem + S_X + buf * 4096);
        int acc[32];
#pragma unroll
        for (int i = 0; i < 32; ++i) acc[i] = 0;

#pragma unroll 4
        for (int k4 = 0; k4 < 16; ++k4) {
            uint4 qa = Qp[k4 * 32 + qi * 2];
            uint4 qb = Qp[k4 * 32 + qi * 2 + 1];
            uint4 xv = Xp[k4 * 16 + ci];
            unsigned qw[8] = { qa.x, qa.y, qa.z, qa.w, qb.x, qb.y, qb.z, qb.w };
            unsigned xw[4] = { xv.x, xv.y, xv.z, xv.w };
#pragma unroll
            for (int i = 0; i < 8; ++i) {
#pragma unroll
                for (int j = 0; j < 4; ++j)
                    acc[i * 4 + j] = dp4a(acc[i * 4 + j], qw[i], xw[j]);
            }
        }

        // ---- epilogue: d = 2*acc - qxx - cxx into swizzled dist tile ----
        {
            int4 cx4 = reinterpret_cast<const int4*>(s_cxq + buf * CTILE)[ci];
            int chunk = ci ^ qi;                 // conflict-free STS (chunk' = ci ^ row>>3)
#pragma unroll
            for (int i = 0; i < 8; ++i) {
                int row = qi * 8 + i;
                int4 dv;
                dv.x = (acc[i * 4 + 0] << 1) - qn[i] - cx4.x;
                dv.y = (acc[i * 4 + 1] << 1) - qn[i] - cx4.y;
                dv.z = (acc[i * 4 + 2] << 1) - qn[i] - cx4.z;
                dv.w = (acc[i * 4 + 3] << 1) - qn[i] - cx4.w;
                *reinterpret_cast<int4*>(smem + S_DIST + row * 256 + (chunk << 4)) = dv;
            }
        }
        __syncthreads();                     // dist complete

        // ---- scan: thread owns (srow, shalf-half of 64 cols), batches of 8 ----
        {
            const uint4* dre = reinterpret_cast<const uint4*>(smem + S_DIST + srow * 256);
            const int cbase = tile * CTILE + shalf * 32;
#pragma unroll 1
            for (int jb = 0; jb < 4; ++jb) {
                int j0 = shalf * 8 + jb * 2;
                uint4 va = dre[j0 ^ m];          // m = srow>>3
                uint4 vb = dre[(j0 + 1) ^ m];
                int d[8] = { (int)va.x, (int)va.y, (int)va.z, (int)va.w,
                             (int)vb.x, (int)vb.y, (int)vb.z, (int)vb.w };
                int dmax = 0x80000000;
#pragma unroll
                for (int e = 0; e < 8; ++e) dmax = max(dmax, d[e]);
                if (dmax > thrI) {
#pragma unroll
                    for (int e = 0; e < 8; ++e) {
                        int dv = d[e];
                        if (dv > thrI) {
                            int jj = cbase + jb * 8 + e;
                            int p = M_KEEP - 1;
                            while (p > 0 && mvI[p - 1] < dv) {   // ties keep earlier index
                                mvI[p] = mvI[p - 1];
                                mi[p] = mi[p - 1];
                                --p;
                            }
                            mvI[p] = dv;
                            mi[p] = jj;
                            thrI = mvI[M_KEEP - 1];
                        }
                    }
                }
            }
        }

        if (tile + 1 < NT) cp_wait0();
        __syncthreads();                     // scan done; next X + cxq ready
    }

    // ---- exact fp32 rescore of this thread's M_KEEP candidates ----
    float* mvF = reinterpret_cast<float*>(mvI);
    const int q = q0 + srow;
    {
        const float* fbf = g_feats + (size_t)b * N_ * C_;
        const float* xxb = g_xx + b * N_;
        const u64* qp = reinterpret_cast<const u64*>(fbf + (size_t)q * C_);
        u64 qv2[32];
#pragma unroll
        for (int i = 0; i < 32; ++i) qv2[i] = qp[i];
        float qxxe = xxb[q];
#pragma unroll 1
        for (int i = 0; i < M_KEEP; ++i) {
            int idx = mi[i];
            const u64* cp = reinterpret_cast<const u64*>(fbf + (size_t)idx * C_);
            u64 a0 = 0, a1 = 0, a2 = 0, a3 = 0;
#pragma unroll
            for (int j = 0; j < 8; ++j) {
                a0 = fma2(qv2[4 * j + 0], cp[4 * j + 0], a0);
                a1 = fma2(qv2[4 * j + 1], cp[4 * j + 1], a1);
                a2 = fma2(qv2[4 * j + 2], cp[4 * j + 2], a2);
                a3 = fma2(qv2[4 * j + 3], cp[4 * j + 3], a3);
            }
            float inner = psum(add2(add2(a0, a1), add2(a2, a3)));
            mvF[i] = 2.f * inner - qxxe - xxb[idx];
        }
        // insertion sort by (val desc, idx asc)
#pragma unroll 1
        for (int i = 1; i < M_KEEP; ++i) {
            float v = mvF[i];
            int ix = mi[i];
            int p = i;
            while (p > 0 && (mvF[p - 1] < v || (mvF[p - 1] == v && mi[p - 1] > ix))) {
                mvF[p] = mvF[p - 1];
                mi[p] = mi[p - 1];
                --p;
            }
            mvF[p] = v;
            mi[p] = ix;
        }
    }

    // write partial list (list id = b*NL + shalf)
    {
        size_t L = (size_t)(b * NL + shalf);
        float* pv = g_pval + (L * N_ + q) * M_KEEP;
        int*   pi = g_pidx + (L * N_ + q) * M_KEEP;
#pragma unroll
        for (int i = 0; i < M_KEEP; ++i) { pv[i] = mvF[i]; pi[i] = mi[i]; }
    }
}

// ---------------- kernel 2b: NL-way merge of partial top lists ----------------
__global__ void __launch_bounds__(256) merge_kernel() {
    int id = blockIdx.x * 256 + threadIdx.x;       // 0 .. B*N-1
    int b = id >> 13;
    int q = id & (N_ - 1);

    const float* pv[NL];
    const int*   pi[NL];
    float hv[NL];
    int   hx[NL];
    int   cur[NL];
#pragma unroll
    for (int c = 0; c < NL; ++c) {
        pv[c] = g_pval + (((size_t)(b * NL + c)) * N_ + q) * M_KEEP;
        pi[c] = g_pidx + (((size_t)(b * NL + c)) * N_ + q) * M_KEEP;
        hv[c] = pv[c][0];
        hx[c] = pi[c][0];
        cur[c] = 0;
    }
    int* og = g_knn + (size_t)id * K_;
#pragma unroll
    for (int s = 0; s < 16; ++s) {
        int best = 0;
#pragma unroll
        for (int c = 1; c < NL; ++c)
            if (hv[c] > hv[best] || (hv[c] == hv[best] && hx[c] < hx[best])) best = c;
        og[s] = hx[best];
        if (++cur[best] < M_KEEP) {
            hv[best] = pv[best][cur[best]];
            hx[best] = pi[best][cur[best]];
        } else {
            hv[best] = -3.4e38f;
            hx[best] = 0x7fffffff;
        }
    }
}

// ---------------- kernel 3: edge conv + max pool ----------------
#define CT  128   // threads = output channels
#define PPB 64    // points per block

__device__ __forceinline__ void cv_issue(const float* fb, const int* s_nidx,
                                         int p0, int pl, int t,
                                         float4* rn, float4* rx) {
#pragma unroll
    for (int s = 0; s < 3; ++s) {
        if (s == 2 && t >= 16) continue;
        int cid = t + s * CT;
        int r = cid >> 4, c4 = cid & 15;
        const float4* xrow = reinterpret_cast<const float4*>(fb + (size_t)(p0 + pl) * C_);
        if (r < 16) {
            int nj = s_nidx[pl * K_ + r];
            rn[s] = reinterpret_cast<const float4*>(fb + (size_t)nj * C_)[c4];
            rx[s] = xrow[c4];
        } else {
            rn[s] = xrow[c4];
        }
    }
}

__device__ __forceinline__ void cv_commit(float4* buf, int t,
                                          const float4* rn, const float4* rx) {
#pragma unroll
    for (int s = 0; s < 3; ++s) {
        if (s == 2 && t >= 16) continue;
        int cid = t + s * CT;
        int r = cid >> 4, c4 = cid & 15;
        float4 v = rn[s];
        if (r < 16) { v.x -= rx[s].x; v.y -= rx[s].y; v.z -= rx[s].z; v.w -= rx[s].w; }
        buf[r * 16 + c4] = v;
    }
}

__global__ void __launch_bounds__(CT) conv_kernel(const float* __restrict__ W,
                                                  const float* __restrict__ bias,
                                                  float* __restrict__ out) {
    __shared__ float4 sbuf[2][17 * 16];
    __shared__ int s_nidx[PPB * K_];

    int b = blockIdx.y;
    int p0 = blockIdx.x * PPB;
    int t = threadIdx.x;
    const float* fb = g_feats + (size_t)b * N_ * C_;

    u64 w2[64];
    {
        const u64* wp = reinterpret_cast<const u64*>(W + (size_t)t * 2 * C_);
#pragma unroll
        for (int i = 0; i < 64; ++i) w2[i] = wp[i];
    }
    float bo = bias[t];

    for (int i = t; i < PPB * K_; i += CT)
        s_nidx[i] = g_knn[(size_t)(b * N_ + p0) * K_ + i];
    __syncthreads();

    float4 rn[3], rx[3];
    cv_issue(fb, s_nidx, p0, 0, t, rn, rx);

    for (int pl = 0; pl < PPB; ++pl) {
        float4* buf = sbuf[pl & 1];
        cv_commit(buf, t, rn, rx);
        __syncthreads();
        if (pl + 1 < PPB) cv_issue(fb, s_nidx, p0, pl + 1, t, rn, rx);

        const ulonglong2* base = reinterpret_cast<const ulonglong2*>(buf);

        u64 a0 = 0, a1 = 0;
#pragma unroll
        for (int i = 0; i < 16; ++i) {
            ulonglong2 u = base[16 * 16 + i];
            a0 = fma2(w2[2 * i], u.x, a0);
            a1 = fma2(w2[2 * i + 1], u.y, a1);
        }
        float aterm = psum(add2(a0, a1));

        float m = -3.4e38f;
#pragma unroll
        for (int k = 0; k < 16; ++k) {
            u64 c0 = 0, c1 = 0, c2 = 0, c3 = 0;
#pragma unroll
            for (int i = 0; i < 8; ++i) {
                ulonglong2 u = base[k * 16 + i];
                ulonglong2 v = base[k * 16 + 8 + i];
                c0 = fma2(w2[32 + 2 * i], u.x, c0);
                c1 = fma2(w2[33 + 2 * i], u.y, c1);
                c2 = fma2(w2[48 + 2 * i], v.x, c2);
                c3 = fma2(w2[49 + 2 * i], v.y, c3);
            }
            float tk = psum(add2(add2(c0, c1), add2(c2, c3)));
            m = fmaxf(m, tk);
        }

        out[(size_t)(b * O_ + t) * N_ + p0 + pl] = aterm + m + bo;
    }
}

// ---------------- launch ----------------
extern "C" void kernel_launch(void* const* d_in, const int* in_sizes, int n_in,
                              void* d_out, int out_size) {
    (void)in_sizes; (void)n_in; (void)out_size;
    const float* x    = (const float*)d_in[0];   // (4, 64, 8192, 1)
    const float* W    = (const float*)d_in[1];   // (128, 128)
    const float* bias = (const float*)d_in[2];   // (128,)
    float* out = (float*)d_out;                  // (4, 128, 8192, 1)

    cudaFuncSetAttribute(knn_kernel, cudaFuncAttributeMaxDynamicSharedMemorySize, KNN_SMEM);

    prep_kernel<<<(B_ * N_) / 256, 256>>>(x);
    knn_kernel<<<dim3(N_ / 128, B_), 256, KNN_SMEM>>>();
    merge_kernel<<<(B_ * N_) / 256, 256>>>();
    conv_kernel<<<dim3(N_ / PPB, B_), CT>>>(W, bias, out);
}

// round 11
// speedup vs baseline: 1.8443x; 1.8443x over previous
#include <cuda_runtime.h>
#include <cstdint>

#define B_ 4
#define N_ 8192
#define C_ 64
#define K_ 16
#define O_ 128

#define CH 2                       // candidate chunks per query
#define QT 256                     // threads = queries per CTA
#define CTILE 128                  // candidates per smem tile
#define CCHUNK (N_ / CH)           // 4096
#define NT (CCHUNK / CTILE)        // 32
#define M_KEEP 24                  // filter margin (>=16)
#define F_ 12                      // FIFO slots per lane
#define QS 20.0f                   // int8 quantization scale

// ---------------- scratch (no allocs allowed) ----------------
__device__ __align__(16) float    g_feats[B_ * N_ * C_];
__device__ __align__(16) float    g_xx[B_ * N_];
__device__ __align__(16) unsigned g_q8[B_ * N_ * 16];     // packed int8 feats (4/word)
__device__ __align__(16) int      g_xxq[B_ * N_];         // quantized sq norms
__device__ __align__(16) int      g_knn[B_ * N_ * K_];
__device__ __align__(16) float    g_pval[B_ * CH * N_ * M_KEEP];
__device__ __align__(16) int      g_pidx[B_ * CH * N_ * M_KEEP];

typedef unsigned long long u64;

// ---------------- packed f32x2 helpers (sm_103a) ----------------
__device__ __forceinline__ u64 fma2(u64 a, u64 b, u64 c) {
    u64 d;
    asm("fma.rn.f32x2 %0, %1, %2, %3;" : "=l"(d) : "l"(a), "l"(b), "l"(c));
    return d;
}
__device__ __forceinline__ u64 add2(u64 a, u64 b) {
    u64 d;
    asm("add.rn.f32x2 %0, %1, %2;" : "=l"(d) : "l"(a), "l"(b));
    return d;
}
__device__ __forceinline__ float psum(u64 v) {
    return __uint_as_float((unsigned)v) + __uint_as_float((unsigned)(v >> 32));
}
__device__ __forceinline__ int dp4a(int acc, unsigned a, unsigned b) {
    int d;
    asm("dp4a.s32.s32 %0, %1, %2, %3;" : "=r"(d) : "r"(a), "r"(b), "r"(acc));
    return d;
}
__device__ __forceinline__ uint32_t smem_u32(const void* p) {
    uint32_t a;
    asm("{ .reg .u64 t; cvta.to.shared.u64 t, %1; cvt.u32.u64 %0, t; }" : "=r"(a) : "l"(p));
    return a;
}
__device__ __forceinline__ void cp_async16(uint32_t dst, const void* src) {
    asm volatile("cp.async.cg.shared.global [%0], [%1], 16;" :: "r"(dst), "l"(src) : "memory");
}
__device__ __forceinline__ void cp_commit() {
    asm volatile("cp.async.commit_group;" ::: "memory");
}
__device__ __forceinline__ void cp_wait1() {
    asm volatile("cp.async.wait_group 1;" ::: "memory");
}
__device__ __forceinline__ void cp_wait0() {
    asm volatile("cp.async.wait_group 0;" ::: "memory");
}

// branch-free insert of (dv, jj) into descending sorted reg arrays (24 slots).
// Matches the while-shift semantics: shift where mv[i-1] < dv; ties keep
// earlier (lower) candidate index above. live=false makes it a no-op.
__device__ __forceinline__ void ins24(int* mv, int* mi, int dv, int jj, bool live) {
    bool c[M_KEEP];
#pragma unroll
    for (int i = 0; i < M_KEEP; ++i) c[i] = live && (mv[i] < dv);
#pragma unroll
    for (int i = M_KEEP - 1; i >= 1; --i) {
        mv[i] = c[i - 1] ? mv[i - 1] : (c[i] ? dv : mv[i]);
        mi[i] = c[i - 1] ? mi[i - 1] : (c[i] ? jj : mi[i]);
    }
    mv[0] = c[0] ? dv : mv[0];
    mi[0] = c[0] ? jj : mi[0];
}

// ---------------- kernel 1: transpose, norms, int8 quantize ----------------
__global__ void __launch_bounds__(256) prep_kernel(const float* __restrict__ x) {
    int idx = blockIdx.x * 256 + threadIdx.x;      // 0 .. B*N-1
    int b = idx >> 13;
    int n = idx & (N_ - 1);
    const float* xb = x + (size_t)b * C_ * N_ + n;
    float v[C_];
    float acc = 0.f;
#pragma unroll
    for (int c = 0; c < C_; ++c) {
        float t = xb[(size_t)c * N_];              // coalesced across threads
        v[c] = t;
        acc = fmaf(t, t, acc);
    }
    float4* fp = reinterpret_cast<float4*>(g_feats + (size_t)idx * C_);
#pragma unroll
    for (int i = 0; i < C_ / 4; ++i)
        fp[i] = make_float4(v[4 * i], v[4 * i + 1], v[4 * i + 2], v[4 * i + 3]);

    // int8 quantization (filter only; exact rescore fixes everything)
    unsigned pk[16];
    int xxq = 0;
#pragma unroll
    for (int g = 0; g < 16; ++g) {
        unsigned p = 0;
#pragma unroll
        for (int e = 0; e < 4; ++e) {
            float s = fminf(fmaxf(v[4 * g + e] * QS, -127.f), 127.f);
            int qi = __float2int_rn(s);
            xxq += qi * qi;
            p |= ((unsigned)qi & 0xFFu) << (8 * e);
        }
        pk[g] = p;
    }
    uint4* qp = reinterpret_cast<uint4*>(g_q8 + (size_t)idx * 16);
#pragma unroll
    for (int i = 0; i < 4; ++i)
        qp[i] = make_uint4(pk[4 * i], pk[4 * i + 1], pk[4 * i + 2], pk[4 * i + 3]);

    g_xxq[idx] = xxq;
    g_xx[idx] = acc;
}

// ---------------- kernel 2: dp4a filter (FIFO + reg-list) + exact fp32 rescore ----------------
// Grid (32, CH, B_): 256 queries x CCHUNK candidates per CTA.
// smem layout (bytes):
#define S_T    0                          // 2 x 8192 int8 candidate tiles
#define S_CXQ  16384                      // 2 x 128 ints
#define S_FD   17408                      // FIFO d:   F_ x 256 ints = 12288
#define S_FI   29696                      // FIFO idx: F_ x 256 ints = 12288
#define KNN_SMEM 41984

__global__ void __launch_bounds__(QT) knn_kernel() {
    extern __shared__ char smem[];
    uint32_t sb = smem_u32(smem);
    const int t = threadIdx.x;
    const int b = blockIdx.z;
    const int ch = blockIdx.y;
    const int q = blockIdx.x * QT + t;
    const int c0 = ch * CCHUNK;

    const unsigned* q8b = g_q8 + (size_t)b * N_ * 16;
    const int* xxqb = g_xxq + b * N_;

    int* s_cxq = reinterpret_cast<int*>(smem + S_CXQ);
    int* s_fd  = reinterpret_cast<int*>(smem + S_FD);
    int* s_fi  = reinterpret_cast<int*>(smem + S_FI);

    // quantized query row (16 words = 64 int8)
    unsigned qw[16];
    {
        const uint4* qp = reinterpret_cast<const uint4*>(q8b + (size_t)q * 16);
#pragma unroll
        for (int i = 0; i < 4; ++i) {
            uint4 u = qp[i];
            qw[4 * i] = u.x; qw[4 * i + 1] = u.y; qw[4 * i + 2] = u.z; qw[4 * i + 3] = u.w;
        }
    }
    const int qxxq = xxqb[q];

    // sorted top-24 list in REGISTERS (descending)
    int mv[M_KEEP], mi[M_KEEP];
#pragma unroll
    for (int i = 0; i < M_KEEP; ++i) { mv[i] = (int)0x80000000; mi[i] = 0; }
    int thr = (int)0x80000000;
    int cnt = 0;

    // tile loader: 128 rows x 64B = 512 x 16B chunks, 2 per thread
    auto issue = [&](int tile, int buf) {
        const char* src = reinterpret_cast<const char*>(q8b + (size_t)(c0 + tile * CTILE) * 16);
        uint32_t dst = sb + S_T + buf * 8192;
        cp_async16(dst + t * 16, src + (size_t)t * 16);
        cp_async16(dst + (t + 256) * 16, src + (size_t)(t + 256) * 16);
        cp_commit();
        if (t < CTILE) s_cxq[buf * CTILE + t] = xxqb[c0 + tile * CTILE + t];
    };
    issue(0, 0);

    for (int tile = 0; tile < NT; ++tile) {
        const int buf = tile & 1;
        if (tile + 1 < NT) { issue(tile + 1, buf ^ 1); cp_wait1(); }
        else               { cp_wait0(); }
        __syncthreads();                    // tile + cxq visible

        const uint4* tb = reinterpret_cast<const uint4*>(smem + S_T + buf * 8192);
        const int* cx = s_cxq + buf * CTILE;
        const int cbase = c0 + tile * CTILE;

#pragma unroll 1
        for (int jb = 0; jb < CTILE / 8; ++jb) {
            const int j0 = jb * 8;
            const uint4* rows = tb + j0 * 4;       // 8 rows x 4 uint4 each

            int acc[8];
#pragma unroll
            for (int c = 0; c < 8; ++c) acc[c] = 0;
#pragma unroll
            for (int i = 0; i < 4; ++i) {
#pragma unroll
                for (int c = 0; c < 8; ++c) {
                    uint4 u = rows[c * 4 + i];     // broadcast LDS.128
                    acc[c] = dp4a(acc[c], qw[4 * i], u.x);
                    acc[c] = dp4a(acc[c], qw[4 * i + 1], u.y);
                    acc[c] = dp4a(acc[c], qw[4 * i + 2], u.z);
                    acc[c] = dp4a(acc[c], qw[4 * i + 3], u.w);
                }
            }

            // branchless append of qualifying candidates to per-lane FIFO
#pragma unroll
            for (int c = 0; c < 8; ++c) {
                int dv = (acc[c] << 1) - qxxq - cx[j0 + c];   // exact quantized neg sq dist
                s_fd[cnt * QT + t] = dv;
                s_fi[cnt * QT + t] = cbase + j0 + c;
                cnt += (dv > thr) ? 1 : 0;
            }

            // rare warp-synchronous flush into register-resident sorted list
            if (__any_sync(0xffffffffu, cnt > F_ - 8)) {
                int m = (int)__reduce_max_sync(0xffffffffu, (unsigned)cnt);
#pragma unroll 1
                for (int e = 0; e < m; ++e) {
                    int dv = s_fd[e * QT + t];
                    int jj = s_fi[e * QT + t];
                    ins24(mv, mi, dv, jj, e < cnt);
                }
                thr = mv[M_KEEP - 1];
                cnt = 0;
            }
        }
        __syncthreads();                    // done with buf before overwrite
    }

    // final flush
    {
        int m = (int)__reduce_max_sync(0xffffffffu, (unsigned)cnt);
#pragma unroll 1
        for (int e = 0; e < m; ++e) {
            int dv = s_fd[e * QT + t];
            int jj = s_fi[e * QT + t];
            ins24(mv, mi, dv, jj, e < cnt);
        }
    }

    // ---- exact fp32 rescore of the M_KEEP candidates (registers, unrolled) ----
    float fv[M_KEEP];
    {
        const float* fbf = g_feats + (size_t)b * N_ * C_;
        const float* xxb = g_xx + b * N_;
        const u64* qp = reinterpret_cast<const u64*>(fbf + (size_t)q * C_);
        u64 qv2[32];
#pragma unroll
        for (int i = 0; i < 32; ++i) qv2[i] = qp[i];
        float qxxe = xxb[q];
#pragma unroll
        for (int i = 0; i < M_KEEP; ++i) {
            int idx = mi[i];
            const u64* cp = reinterpret_cast<const u64*>(fbf + (size_t)idx * C_);
            u64 a0 = 0, a1 = 0, a2 = 0, a3 = 0;
#pragma unroll
            for (int j = 0; j < 8; ++j) {
                a0 = fma2(qv2[4 * j + 0], cp[4 * j + 0], a0);
                a1 = fma2(qv2[4 * j + 1], cp[4 * j + 1], a1);
                a2 = fma2(qv2[4 * j + 2], cp[4 * j + 2], a2);
                a3 = fma2(qv2[4 * j + 3], cp[4 * j + 3], a3);
            }
            float inner = psum(add2(add2(a0, a1), add2(a2, a3)));
            fv[i] = 2.f * inner - qxxe - xxb[idx];
        }
    }

    // odd-even transposition sort by (val desc, idx asc) — static indexing
#pragma unroll
    for (int pass = 0; pass < M_KEEP; ++pass) {
#pragma unroll
        for (int i = (pass & 1); i + 1 < M_KEEP; i += 2) {
            bool sw = (fv[i + 1] > fv[i]) || (fv[i + 1] == fv[i] && mi[i + 1] < mi[i]);
            float tv = sw ? fv[i + 1] : fv[i];
            fv[i + 1] = sw ? fv[i] : fv[i + 1];
            fv[i] = tv;
            int ti = sw ? mi[i + 1] : mi[i];
            mi[i + 1] = sw ? mi[i] : mi[i + 1];
            mi[i] = ti;
        }
    }

    // write partial list (list id = b*CH + ch)
    {
        size_t L = (size_t)(b * CH + ch);
        float* pv = g_pval + (L * N_ + q) * M_KEEP;
        int*   pi = g_pidx + (L * N_ + q) * M_KEEP;
#pragma unroll
        for (int i = 0; i < M_KEEP; ++i) { pv[i] = fv[i]; pi[i] = mi[i]; }
    }
}

// ---------------- kernel 2b: CH-way merge of partial top lists ----------------
__global__ void __launch_bounds__(256) merge_kernel() {
    int id = blockIdx.x * 256 + threadIdx.x;       // 0 .. B*N-1
    int b = id >> 13;
    int q = id & (N_ - 1);

    const float* pv[CH];
    const int*   pi[CH];
    float hv[CH];
    int   hx[CH];
    int   cur[CH];
#pragma unroll
    for (int c = 0; c < CH; ++c) {
        pv[c] = g_pval + (((size_t)(b * CH + c)) * N_ + q) * M_KEEP;
        pi[c] = g_pidx + (((size_t)(b * CH + c)) * N_ + q) * M_KEEP;
        hv[c] = pv[c][0];
        hx[c] = pi[c][0];
        cur[c] = 0;
    }
    int* og = g_knn + (size_t)id * K_;
#pragma unroll
    for (int s = 0; s < 16; ++s) {
        int best = 0;
#pragma unroll
        for (int c = 1; c < CH; ++c)
            if (hv[c] > hv[best] || (hv[c] == hv[best] && hx[c] < hx[best])) best = c;
        og[s] = hx[best];
        if (++cur[best] < M_KEEP) {
            hv[best] = pv[best][cur[best]];
            hx[best] = pi[best][cur[best]];
        } else {
            hv[best] = -3.4e38f;
            hx[best] = 0x7fffffff;
        }
    }
}

// ---------------- kernel 3: edge conv + max pool ----------------
#define CT  128   // threads = output channels
#define PPB 64    // points per block

__device__ __forceinline__ void cv_issue(const float* fb, const int* s_nidx,
                                         int p0, int pl, int t,
                                         float4* rn, float4* rx) {
#pragma unroll
    for (int s = 0; s < 3; ++s) {
        if (s == 2 && t >= 16) continue;
        int cid = t + s * CT;
        int r = cid >> 4, c4 = cid & 15;
        const float4* xrow = reinterpret_cast<const float4*>(fb + (size_t)(p0 + pl) * C_);
        if (r < 16) {
            int nj = s_nidx[pl * K_ + r];
            rn[s] = reinterpret_cast<const float4*>(fb + (size_t)nj * C_)[c4];
            rx[s] = xrow[c4];
        } else {
            rn[s] = xrow[c4];
        }
    }
}

__device__ __forceinline__ void cv_commit(float4* buf, int t,
                                          const float4* rn, const float4* rx) {
#pragma unroll
    for (int s = 0; s < 3; ++s) {
        if (s == 2 && t >= 16) continue;
        int cid = t + s * CT;
        int r = cid >> 4, c4 = cid & 15;
        float4 v = rn[s];
        if (r < 16) { v.x -= rx[s].x; v.y -= rx[s].y; v.z -= rx[s].z; v.w -= rx[s].w; }
        buf[r * 16 + c4] = v;
    }
}

__global__ void __launch_bounds__(CT) conv_kernel(const float* __restrict__ W,
                                                  const float* __restrict__ bias,
                                                  float* __restrict__ out) {
    __shared__ float4 sbuf[2][17 * 16];
    __shared__ int s_nidx[PPB * K_];

    int b = blockIdx.y;
    int p0 = blockIdx.x * PPB;
    int t = threadIdx.x;
    const float* fb = g_feats + (size_t)b * N_ * C_;

    u64 w2[64];
    {
        const u64* wp = reinterpret_cast<const u64*>(W + (size_t)t * 2 * C_);
#pragma unroll
        for (int i = 0; i < 64; ++i) w2[i] = wp[i];
    }
    float bo = bias[t];

    for (int i = t; i < PPB * K_; i += CT)
        s_nidx[i] = g_knn[(size_t)(b * N_ + p0) * K_ + i];
    __syncthreads();

    float4 rn[3], rx[3];
    cv_issue(fb, s_nidx, p0, 0, t, rn, rx);

    for (int pl = 0; pl < PPB; ++pl) {
        float4* buf = sbuf[pl & 1];
        cv_commit(buf, t, rn, rx);
        __syncthreads();
        if (pl + 1 < PPB) cv_issue(fb, s_nidx, p0, pl + 1, t, rn, rx);

        const ulonglong2* base = reinterpret_cast<const ulonglong2*>(buf);

        u64 a0 = 0, a1 = 0;
#pragma unroll
        for (int i = 0; i < 16; ++i) {
            ulonglong2 u = base[16 * 16 + i];
            a0 = fma2(w2[2 * i], u.x, a0);
            a1 = fma2(w2[2 * i + 1], u.y, a1);
        }
        float aterm = psum(add2(a0, a1));

        float m = -3.4e38f;
#pragma unroll
        for (int k = 0; k < 16; ++k) {
            u64 c0 = 0, c1 = 0, c2 = 0, c3 = 0;
#pragma unroll
            for (int i = 0; i < 8; ++i) {
                ulonglong2 u = base[k * 16 + i];
                ulonglong2 v = base[k * 16 + 8 + i];
                c0 = fma2(w2[32 + 2 * i], u.x, c0);
                c1 = fma2(w2[33 + 2 * i], u.y, c1);
                c2 = fma2(w2[48 + 2 * i], v.x, c2);
                c3 = fma2(w2[49 + 2 * i], v.y, c3);
            }
            float tk = psum(add2(add2(c0, c1), add2(c2, c3)));
            m = fmaxf(m, tk);
        }

        out[(size_t)(b * O_ + t) * N_ + p0 + pl] = aterm + m + bo;
    }
}

// ---------------- launch ----------------
extern "C" void kernel_launch(void* const* d_in, const int* in_sizes, int n_in,
                              void* d_out, int out_size) {
    (void)in_sizes; (void)n_in; (void)out_size;
    const float* x    = (const float*)d_in[0];   // (4, 64, 8192, 1)
    const float* W    = (const float*)d_in[1];   // (128, 128)
    const float* bias = (const float*)d_in[2];   // (128,)
    float* out = (float*)d_out;                  // (4, 128, 8192, 1)

    cudaFuncSetAttribute(knn_kernel, cudaFuncAttributeMaxDynamicSharedMemorySize, KNN_SMEM);

    prep_kernel<<<(B_ * N_) / 256, 256>>>(x);
    knn_kernel<<<dim3(N_ / QT, CH, B_), QT, KNN_SMEM>>>();
    merge_kernel<<<(B_ * N_) / 256, 256>>>();
    conv_kernel<<<dim3(N_ / PPB, B_), CT>>>(W, bias, out);
}

// round 12
// speedup vs baseline: 2.2123x; 1.1995x over previous
#include <cuda_runtime.h>
#include <cstdint>

#define B_ 4
#define N_ 8192
#define C_ 64
#define K_ 16
#define O_ 128

#define CH 2                       // candidate chunks per query
#define QT 256                     // threads = queries per CTA
#define CTILE 128                  // candidates per smem tile
#define CCHUNK (N_ / CH)           // 4096
#define NT (CCHUNK / CTILE)        // 32
#define M_KEEP 24                  // filter margin (>=16)
#define F_ 12                      // FIFO slots per lane
#define QS 20.0f                   // int8 quantization scale

// ---------------- scratch (no allocs allowed) ----------------
__device__ __align__(16) float    g_feats[B_ * N_ * C_];
__device__ __align__(16) float    g_xx[B_ * N_];
__device__ __align__(16) unsigned g_q8[B_ * N_ * 16];     // packed int8 feats (4/word)
__device__ __align__(16) int      g_xxq[B_ * N_];         // quantized sq norms
__device__ __align__(16) int      g_knn[B_ * N_ * K_];
__device__ __align__(16) float    g_pval[B_ * CH * N_ * M_KEEP];
__device__ __align__(16) int      g_pidx[B_ * CH * N_ * M_KEEP];
__device__ __align__(16) float    g_Y[B_ * N_ * O_];      // W2 . x_n
__device__ __align__(16) float    g_Z[B_ * N_ * O_];      // (W1-W2) . x_n

typedef unsigned long long u64;

// ---------------- packed f32x2 helpers (sm_103a) ----------------
__device__ __forceinline__ u64 fma2(u64 a, u64 b, u64 c) {
    u64 d;
    asm("fma.rn.f32x2 %0, %1, %2, %3;" : "=l"(d) : "l"(a), "l"(b), "l"(c));
    return d;
}
__device__ __forceinline__ u64 add2(u64 a, u64 b) {
    u64 d;
    asm("add.rn.f32x2 %0, %1, %2;" : "=l"(d) : "l"(a), "l"(b));
    return d;
}
__device__ __forceinline__ u64 dup2(float a) {
    u64 d;
    asm("mov.b64 %0, {%1, %1};" : "=l"(d) : "f"(a));
    return d;
}
__device__ __forceinline__ float psum(u64 v) {
    return __uint_as_float((unsigned)v) + __uint_as_float((unsigned)(v >> 32));
}
__device__ __forceinline__ int dp4a(int acc, unsigned a, unsigned b) {
    int d;
    asm("dp4a.s32.s32 %0, %1, %2, %3;" : "=r"(d) : "r"(a), "r"(b), "r"(acc));
    return d;
}
__device__ __forceinline__ uint32_t smem_u32(const void* p) {
    uint32_t a;
    asm("{ .reg .u64 t; cvta.to.shared.u64 t, %1; cvt.u32.u64 %0, t; }" : "=r"(a) : "l"(p));
    return a;
}
__device__ __forceinline__ void cp_async16(uint32_t dst, const void* src) {
    asm volatile("cp.async.cg.shared.global [%0], [%1], 16;" :: "r"(dst), "l"(src) : "memory");
}
__device__ __forceinline__ void cp_commit() {
    asm volatile("cp.async.commit_group;" ::: "memory");
}
__device__ __forceinline__ void cp_wait1() {
    asm volatile("cp.async.wait_group 1;" ::: "memory");
}
__device__ __forceinline__ void cp_wait0() {
    asm volatile("cp.async.wait_group 0;" ::: "memory");
}

// branch-free insert of (dv, jj) into descending sorted reg arrays (24 slots).
__device__ __forceinline__ void ins24(int* mv, int* mi, int dv, int jj, bool live) {
    bool c[M_KEEP];
#pragma unroll
    for (int i = 0; i < M_KEEP; ++i) c[i] = live && (mv[i] < dv);
#pragma unroll
    for (int i = M_KEEP - 1; i >= 1; --i) {
        mv[i] = c[i - 1] ? mv[i - 1] : (c[i] ? dv : mv[i]);
        mi[i] = c[i - 1] ? mi[i - 1] : (c[i] ? jj : mi[i]);
    }
    mv[0] = c[0] ? dv : mv[0];
    mi[0] = c[0] ? jj : mi[0];
}

// ---------------- kernel 1: transpose, norms, int8 quantize ----------------
__global__ void __launch_bounds__(256) prep_kernel(const float* __restrict__ x) {
    int idx = blockIdx.x * 256 + threadIdx.x;      // 0 .. B*N-1
    int b = idx >> 13;
    int n = idx & (N_ - 1);
    const float* xb = x + (size_t)b * C_ * N_ + n;
    float v[C_];
    float acc = 0.f;
#pragma unroll
    for (int c = 0; c < C_; ++c) {
        float t = xb[(size_t)c * N_];              // coalesced across threads
        v[c] = t;
        acc = fmaf(t, t, acc);
    }
    float4* fp = reinterpret_cast<float4*>(g_feats + (size_t)idx * C_);
#pragma unroll
    for (int i = 0; i < C_ / 4; ++i)
        fp[i] = make_float4(v[4 * i], v[4 * i + 1], v[4 * i + 2], v[4 * i + 3]);

    // int8 quantization (filter only; exact rescore fixes everything)
    unsigned pk[16];
    int xxq = 0;
#pragma unroll
    for (int g = 0; g < 16; ++g) {
        unsigned p = 0;
#pragma unroll
        for (int e = 0; e < 4; ++e) {
            float s = fminf(fmaxf(v[4 * g + e] * QS, -127.f), 127.f);
            int qi = __float2int_rn(s);
            xxq += qi * qi;
            p |= ((unsigned)qi & 0xFFu) << (8 * e);
        }
        pk[g] = p;
    }
    uint4* qp = reinterpret_cast<uint4*>(g_q8 + (size_t)idx * 16);
#pragma unroll
    for (int i = 0; i < 4; ++i)
        qp[i] = make_uint4(pk[4 * i], pk[4 * i + 1], pk[4 * i + 2], pk[4 * i + 3]);

    g_xxq[idx] = xxq;
    g_xx[idx] = acc;
}

// ---------------- kernel 2: dp4a filter (FIFO + reg-list) + exact fp32 rescore ----------------
// (identical to R11 — proven)
#define S_T    0                          // 2 x 8192 int8 candidate tiles
#define S_CXQ  16384                      // 2 x 128 ints
#define S_FD   17408                      // FIFO d:   F_ x 256 ints = 12288
#define S_FI   29696                      // FIFO idx: F_ x 256 ints = 12288
#define KNN_SMEM 41984

__global__ void __launch_bounds__(QT) knn_kernel() {
    extern __shared__ char smem[];
    uint32_t sb = smem_u32(smem);
    const int t = threadIdx.x;
    const int b = blockIdx.z;
    const int ch = blockIdx.y;
    const int q = blockIdx.x * QT + t;
    const int c0 = ch * CCHUNK;

    const unsigned* q8b = g_q8 + (size_t)b * N_ * 16;
    const int* xxqb = g_xxq + b * N_;

    int* s_cxq = reinterpret_cast<int*>(smem + S_CXQ);
    int* s_fd  = reinterpret_cast<int*>(smem + S_FD);
    int* s_fi  = reinterpret_cast<int*>(smem + S_FI);

    unsigned qw[16];
    {
        const uint4* qp = reinterpret_cast<const uint4*>(q8b + (size_t)q * 16);
#pragma unroll
        for (int i = 0; i < 4; ++i) {
            uint4 u = qp[i];
            qw[4 * i] = u.x; qw[4 * i + 1] = u.y; qw[4 * i + 2] = u.z; qw[4 * i + 3] = u.w;
        }
    }
    const int qxxq = xxqb[q];

    int mv[M_KEEP], mi[M_KEEP];
#pragma unroll
    for (int i = 0; i < M_KEEP; ++i) { mv[i] = (int)0x80000000; mi[i] = 0; }
    int thr = (int)0x80000000;
    int cnt = 0;

    auto issue = [&](int tile, int buf) {
        const char* src = reinterpret_cast<const char*>(q8b + (size_t)(c0 + tile * CTILE) * 16);
        uint32_t dst = sb + S_T + buf * 8192;
        cp_async16(dst + t * 16, src + (size_t)t * 16);
        cp_async16(dst + (t + 256) * 16, src + (size_t)(t + 256) * 16);
        cp_commit();
        if (t < CTILE) s_cxq[buf * CTILE + t] = xxqb[c0 + tile * CTILE + t];
    };
    issue(0, 0);

    for (int tile = 0; tile < NT; ++tile) {
        const int buf = tile & 1;
        if (tile + 1 < NT) { issue(tile + 1, buf ^ 1); cp_wait1(); }
        else               { cp_wait0(); }
        __syncthreads();

        const uint4* tb = reinterpret_cast<const uint4*>(smem + S_T + buf * 8192);
        const int* cx = s_cxq + buf * CTILE;
        const int cbase = c0 + tile * CTILE;

#pragma unroll 1
        for (int jb = 0; jb < CTILE / 8; ++jb) {
            const int j0 = jb * 8;
            const uint4* rows = tb + j0 * 4;

            int acc[8];
#pragma unroll
            for (int c = 0; c < 8; ++c) acc[c] = 0;
#pragma unroll
            for (int i = 0; i < 4; ++i) {
#pragma unroll
                for (int c = 0; c < 8; ++c) {
                    uint4 u = rows[c * 4 + i];
                    acc[c] = dp4a(acc[c], qw[4 * i], u.x);
                    acc[c] = dp4a(acc[c], qw[4 * i + 1], u.y);
                    acc[c] = dp4a(acc[c], qw[4 * i + 2], u.z);
                    acc[c] = dp4a(acc[c], qw[4 * i + 3], u.w);
                }
            }

#pragma unroll
            for (int c = 0; c < 8; ++c) {
                int dv = (acc[c] << 1) - qxxq - cx[j0 + c];
                s_fd[cnt * QT + t] = dv;
                s_fi[cnt * QT + t] = cbase + j0 + c;
                cnt += (dv > thr) ? 1 : 0;
            }

            if (__any_sync(0xffffffffu, cnt > F_ - 8)) {
                int m = (int)__reduce_max_sync(0xffffffffu, (unsigned)cnt);
#pragma unroll 1
                for (int e = 0; e < m; ++e) {
                    int dv = s_fd[e * QT + t];
                    int jj = s_fi[e * QT + t];
                    ins24(mv, mi, dv, jj, e < cnt);
                }
                thr = mv[M_KEEP - 1];
                cnt = 0;
            }
        }
        __syncthreads();
    }

    {
        int m = (int)__reduce_max_sync(0xffffffffu, (unsigned)cnt);
#pragma unroll 1
        for (int e = 0; e < m; ++e) {
            int dv = s_fd[e * QT + t];
            int jj = s_fi[e * QT + t];
            ins24(mv, mi, dv, jj, e < cnt);
        }
    }

    // exact fp32 rescore
    float fv[M_KEEP];
    {
        const float* fbf = g_feats + (size_t)b * N_ * C_;
        const float* xxb = g_xx + b * N_;
        const u64* qp = reinterpret_cast<const u64*>(fbf + (size_t)q * C_);
        u64 qv2[32];
#pragma unroll
        for (int i = 0; i < 32; ++i) qv2[i] = qp[i];
        float qxxe = xxb[q];
#pragma unroll
        for (int i = 0; i < M_KEEP; ++i) {
            int idx = mi[i];
            const u64* cp = reinterpret_cast<const u64*>(fbf + (size_t)idx * C_);
            u64 a0 = 0, a1 = 0, a2 = 0, a3 = 0;
#pragma unroll
            for (int j = 0; j < 8; ++j) {
                a0 = fma2(qv2[4 * j + 0], cp[4 * j + 0], a0);
                a1 = fma2(qv2[4 * j + 1], cp[4 * j + 1], a1);
                a2 = fma2(qv2[4 * j + 2], cp[4 * j + 2], a2);
                a3 = fma2(qv2[4 * j + 3], cp[4 * j + 3], a3);
            }
            float inner = psum(add2(add2(a0, a1), add2(a2, a3)));
            fv[i] = 2.f * inner - qxxe - xxb[idx];
        }
    }

    // odd-even sort by (val desc, idx asc)
#pragma unroll
    for (int pass = 0; pass < M_KEEP; ++pass) {
#pragma unroll
        for (int i = (pass & 1); i + 1 < M_KEEP; i += 2) {
            bool sw = (fv[i + 1] > fv[i]) || (fv[i + 1] == fv[i] && mi[i + 1] < mi[i]);
            float tv = sw ? fv[i + 1] : fv[i];
            fv[i + 1] = sw ? fv[i] : fv[i + 1];
            fv[i] = tv;
            int ti = sw ? mi[i + 1] : mi[i];
            mi[i + 1] = sw ? mi[i] : mi[i + 1];
            mi[i] = ti;
        }
    }

    {
        size_t L = (size_t)(b * CH + ch);
        float* pv = g_pval + (L * N_ + q) * M_KEEP;
        int*   pi = g_pidx + (L * N_ + q) * M_KEEP;
#pragma unroll
        for (int i = 0; i < M_KEEP; ++i) { pv[i] = fv[i]; pi[i] = mi[i]; }
    }
}

// ---------------- kernel 2b: CH-way merge of partial top lists ----------------
__global__ void __launch_bounds__(256) merge_kernel() {
    int id = blockIdx.x * 256 + threadIdx.x;       // 0 .. B*N-1
    int b = id >> 13;
    int q = id & (N_ - 1);

    const float* pv[CH];
    const int*   pi[CH];
    float hv[CH];
    int   hx[CH];
    int   cur[CH];
#pragma unroll
    for (int c = 0; c < CH; ++c) {
        pv[c] = g_pval + (((size_t)(b * CH + c)) * N_ + q) * M_KEEP;
        pi[c] = g_pidx + (((size_t)(b * CH + c)) * N_ + q) * M_KEEP;
        hv[c] = pv[c][0];
        hx[c] = pi[c][0];
        cur[c] = 0;
    }
    int* og = g_knn + (size_t)id * K_;
#pragma unroll
    for (int s = 0; s < 16; ++s) {
        int best = 0;
#pragma unroll
        for (int c = 1; c < CH; ++c)
            if (hv[c] > hv[best] || (hv[c] == hv[best] && hx[c] < hx[best])) best = c;
        og[s] = hx[best];
        if (++cur[best] < M_KEEP) {
            hv[best] = pv[best][cur[best]];
            hx[best] = pi[best][cur[best]];
        } else {
            hv[best] = -3.4e38f;
            hx[best] = 0x7fffffff;
        }
    }
}

// ---------------- kernel 3a: per-point GEMM  Y = W2.x, Z = (W1-W2).x ----------------
// Grid (N/64, B_), 128 threads = output channels, 64 points per CTA.
__global__ void __launch_bounds__(128) zy_kernel(const float* __restrict__ W) {
    const int t = threadIdx.x;                      // channel
    const int b = blockIdx.y;
    const int p0 = blockIdx.x * 64;

    // w2r = W2 row; wzr = (W1 - W2) row, both packed f32x2
    u64 w2r[32], wzr[32];
    {
        const u64* wp = reinterpret_cast<const u64*>(W + (size_t)t * 2 * C_);
        const u64 neg1 = dup2(-1.f);
#pragma unroll
        for (int i = 0; i < 32; ++i) {
            u64 w1 = wp[i];
            u64 w2 = wp[32 + i];
            w2r[i] = w2;
            wzr[i] = fma2(w2, neg1, w1);            // w1 - w2 (exact)
        }
    }

    const float* fb = g_feats + (size_t)b * N_ * C_;
    float* Yb = g_Y + ((size_t)b * N_ + p0) * O_;
    float* Zb = g_Z + ((size_t)b * N_ + p0) * O_;

#pragma unroll 1
    for (int pl = 0; pl < 64; ++pl) {
        const ulonglong2* xp = reinterpret_cast<const ulonglong2*>(fb + (size_t)(p0 + pl) * C_);
        u64 y0 = 0, y1 = 0, y2 = 0, y3 = 0;
        u64 z0 = 0, z1 = 0, z2 = 0, z3 = 0;
#pragma unroll
        for (int i = 0; i < 8; ++i) {
            ulonglong2 ua = xp[2 * i];
            ulonglong2 ub = xp[2 * i + 1];
            y0 = fma2(w2r[4 * i + 0], ua.x, y0);
            y1 = fma2(w2r[4 * i + 1], ua.y, y1);
            y2 = fma2(w2r[4 * i + 2], ub.x, y2);
            y3 = fma2(w2r[4 * i + 3], ub.y, y3);
            z0 = fma2(wzr[4 * i + 0], ua.x, z0);
            z1 = fma2(wzr[4 * i + 1], ua.y, z1);
            z2 = fma2(wzr[4 * i + 2], ub.x, z2);
            z3 = fma2(wzr[4 * i + 3], ub.y, z3);
        }
        Yb[pl * O_ + t] = psum(add2(add2(y0, y1), add2(y2, y3)));
        Zb[pl * O_ + t] = psum(add2(add2(z0, z1), add2(z2, z3)));
    }
}

// ---------------- kernel 3b: gather-max epilogue ----------------
// out[b][o][n] = Z[n][o] + max_k Y[nn_k][o] + bias[o]
#define GPB 64
__global__ void __launch_bounds__(128) gmax_kernel(const float* __restrict__ bias,
                                                   float* __restrict__ out) {
    __shared__ int   s_nidx[GPB * K_];
    __shared__ float s_res[128 * 65];               // [channel][point], pad 65 vs bank conflicts

    const int t = threadIdx.x;                      // channel
    const int b = blockIdx.y;
    const int p0 = blockIdx.x * GPB;

    const float* Yb = g_Y + (size_t)b * N_ * O_;
    const float* Zb = g_Z + (size_t)b * N_ * O_;
    const float bo = bias[t];

    for (int i = t; i < GPB * K_; i += 128)
        s_nidx[i] = g_knn[(size_t)(b * N_ + p0) * K_ + i];
    __syncthreads();

#pragma unroll 1
    for (int pl = 0; pl < GPB; ++pl) {
        const int* nn = s_nidx + pl * K_;
        float m = -3.4e38f;
#pragma unroll
        for (int k = 0; k < K_; ++k)
            m = fmaxf(m, Yb[(size_t)nn[k] * O_ + t]);   // coalesced row reads
        float z = Zb[(size_t)(p0 + pl) * O_ + t];
        s_res[t * 65 + pl] = z + m + bo;
    }
    __syncthreads();

    // coalesced transposed write: out[(b*O+o)*N + p0+p]
#pragma unroll
    for (int i = 0; i < 64; ++i) {
        int idx = t + i * 128;                      // 0..8191
        int o = idx >> 6;                           // channel
        int p = idx & 63;                           // point
        out[((size_t)(b * O_ + o)) * N_ + p0 + p] = s_res[o * 65 + p];
    }
}

// ---------------- launch ----------------
extern "C" void kernel_launch(void* const* d_in, const int* in_sizes, int n_in,
                              void* d_out, int out_size) {
    (void)in_sizes; (void)n_in; (void)out_size;
    const float* x    = (const float*)d_in[0];   // (4, 64, 8192, 1)
    const float* W    = (const float*)d_in[1];   // (128, 128)
    const float* bias = (const float*)d_in[2];   // (128,)
    float* out = (float*)d_out;                  // (4, 128, 8192, 1)

    cudaFuncSetAttribute(knn_kernel, cudaFuncAttributeMaxDynamicSharedMemorySize, KNN_SMEM);

    prep_kernel<<<(B_ * N_) / 256, 256>>>(x);
    knn_kernel<<<dim3(N_ / QT, CH, B_), QT, KNN_SMEM>>>();
    merge_kernel<<<(B_ * N_) / 256, 256>>>();
    zy_kernel<<<dim3(N_ / 64, B_), 128>>>(W);
    gmax_kernel<<<dim3(N_ / GPB, B_), 128>>>(bias, out);
}

// round 13
// speedup vs baseline: 2.4369x; 1.1015x over previous
#include <cuda_runtime.h>
#include <cstdint>

#define B_ 4
#define N_ 8192
#define C_ 64
#define K_ 16
#define O_ 128

#define CH 2                       // candidate chunks per query
#define QT 256                     // threads per CTA
#define QP 2                       // queries per thread
#define CTILE 128                  // candidates per smem tile
#define CCHUNK (N_ / CH)           // 4096
#define NT (CCHUNK / CTILE)        // 32
#define M_KEEP 24                  // filter margin (>=16)
#define F_ 12                      // FIFO slots per lane per query
#define QS 20.0f                   // int8 quantization scale

// ---------------- scratch (no allocs allowed) ----------------
__device__ __align__(16) float    g_feats[B_ * N_ * C_];
__device__ __align__(16) float    g_xx[B_ * N_];
__device__ __align__(16) unsigned g_q8[B_ * N_ * 16];     // packed int8 feats (4/word)
__device__ __align__(16) int      g_xxq[B_ * N_];         // quantized sq norms
__device__ __align__(16) int      g_knn[B_ * N_ * K_];
__device__ __align__(16) float    g_pval[B_ * CH * N_ * M_KEEP];
__device__ __align__(16) int      g_pidx[B_ * CH * N_ * M_KEEP];
__device__ __align__(16) float    g_Y[B_ * N_ * O_];      // W2 . x_n
__device__ __align__(16) float    g_Z[B_ * N_ * O_];      // (W1-W2) . x_n

typedef unsigned long long u64;

// ---------------- packed f32x2 helpers (sm_103a) ----------------
__device__ __forceinline__ u64 fma2(u64 a, u64 b, u64 c) {
    u64 d;
    asm("fma.rn.f32x2 %0, %1, %2, %3;" : "=l"(d) : "l"(a), "l"(b), "l"(c));
    return d;
}
__device__ __forceinline__ u64 add2(u64 a, u64 b) {
    u64 d;
    asm("add.rn.f32x2 %0, %1, %2;" : "=l"(d) : "l"(a), "l"(b));
    return d;
}
__device__ __forceinline__ u64 dup2(float a) {
    u64 d;
    asm("mov.b64 %0, {%1, %1};" : "=l"(d) : "f"(a));
    return d;
}
__device__ __forceinline__ float psum(u64 v) {
    return __uint_as_float((unsigned)v) + __uint_as_float((unsigned)(v >> 32));
}
__device__ __forceinline__ int dp4a(int acc, unsigned a, unsigned b) {
    int d;
    asm("dp4a.s32.s32 %0, %1, %2, %3;" : "=r"(d) : "r"(a), "r"(b), "r"(acc));
    return d;
}
__device__ __forceinline__ uint32_t smem_u32(const void* p) {
    uint32_t a;
    asm("{ .reg .u64 t; cvta.to.shared.u64 t, %1; cvt.u32.u64 %0, t; }" : "=r"(a) : "l"(p));
    return a;
}
__device__ __forceinline__ void cp_async16(uint32_t dst, const void* src) {
    asm volatile("cp.async.cg.shared.global [%0], [%1], 16;" :: "r"(dst), "l"(src) : "memory");
}
__device__ __forceinline__ void cp_commit() {
    asm volatile("cp.async.commit_group;" ::: "memory");
}
__device__ __forceinline__ void cp_wait1() {
    asm volatile("cp.async.wait_group 1;" ::: "memory");
}
__device__ __forceinline__ void cp_wait0() {
    asm volatile("cp.async.wait_group 0;" ::: "memory");
}

// predicated FIFO push: store (dv, jj) at slot `cnt` ONLY when dv > thr (no branch,
// no crossbar when predicated off); caller increments cnt separately.
__device__ __forceinline__ void fifo_push(uint32_t fd_base, uint32_t fi_base,
                                          int cnt, int dv, int jj, int thr) {
    uint32_t off = (uint32_t)cnt << 10;    // cnt * QT * 4
    asm volatile(
        "{\n\t.reg .pred p;\n\t"
        "setp.gt.s32 p, %0, %1;\n\t"
        "@p st.shared.b32 [%2], %0;\n\t"
        "@p st.shared.b32 [%3], %4;\n\t}"
        :: "r"(dv), "r"(thr), "r"(fd_base + off), "r"(fi_base + off), "r"(jj)
        : "memory");
}

// branch-free insert of (dv, jj) into descending sorted reg arrays (24 slots).
__device__ __forceinline__ void ins24(int* mv, int* mi, int dv, int jj, bool live) {
    bool c[M_KEEP];
#pragma unroll
    for (int i = 0; i < M_KEEP; ++i) c[i] = live && (mv[i] < dv);
#pragma unroll
    for (int i = M_KEEP - 1; i >= 1; --i) {
        mv[i] = c[i - 1] ? mv[i - 1] : (c[i] ? dv : mv[i]);
        mi[i] = c[i - 1] ? mi[i - 1] : (c[i] ? jj : mi[i]);
    }
    mv[0] = c[0] ? dv : mv[0];
    mi[0] = c[0] ? jj : mi[0];
}

// ---------------- kernel 1: transpose, norms, int8 quantize ----------------
__global__ void __launch_bounds__(256) prep_kernel(const float* __restrict__ x) {
    int idx = blockIdx.x * 256 + threadIdx.x;      // 0 .. B*N-1
    int b = idx >> 13;
    int n = idx & (N_ - 1);
    const float* xb = x + (size_t)b * C_ * N_ + n;
    float v[C_];
    float acc = 0.f;
#pragma unroll
    for (int c = 0; c < C_; ++c) {
        float t = xb[(size_t)c * N_];              // coalesced across threads
        v[c] = t;
        acc = fmaf(t, t, acc);
    }
    float4* fp = reinterpret_cast<float4*>(g_feats + (size_t)idx * C_);
#pragma unroll
    for (int i = 0; i < C_ / 4; ++i)
        fp[i] = make_float4(v[4 * i], v[4 * i + 1], v[4 * i + 2], v[4 * i + 3]);

    unsigned pk[16];
    int xxq = 0;
#pragma unroll
    for (int g = 0; g < 16; ++g) {
        unsigned p = 0;
#pragma unroll
        for (int e = 0; e < 4; ++e) {
            float s = fminf(fmaxf(v[4 * g + e] * QS, -127.f), 127.f);
            int qi = __float2int_rn(s);
            xxq += qi * qi;
            p |= ((unsigned)qi & 0xFFu) << (8 * e);
        }
        pk[g] = p;
    }
    uint4* qp = reinterpret_cast<uint4*>(g_q8 + (size_t)idx * 16);
#pragma unroll
    for (int i = 0; i < 4; ++i)
        qp[i] = make_uint4(pk[4 * i], pk[4 * i + 1], pk[4 * i + 2], pk[4 * i + 3]);

    g_xxq[idx] = xxq;
    g_xx[idx] = acc;
}

// ---------------- kernel 2: dp4a filter (2 queries/thread) + exact fp32 rescore ----------------
// Grid (N/512, CH, B_) = 128 CTAs; 256 threads; thread owns queries q0+t, q0+t+256.
// smem layout (bytes):
#define S_T    0                          // 2 x 8192 int8 candidate tiles
#define S_CXQ  16384                      // 2 x 128 ints
#define S_FDA  17408                      // FIFO A d:   F_ x 256 ints
#define S_FIA  29696
#define S_FDB  41984
#define S_FIB  54272
#define KNN_SMEM 66560

__global__ void __launch_bounds__(QT) knn_kernel() {
    extern __shared__ char smem[];
    uint32_t sb = smem_u32(smem);
    const int t = threadIdx.x;
    const int b = blockIdx.z;
    const int ch = blockIdx.y;
    const int q0 = blockIdx.x * (QT * QP);
    const int qA = q0 + t;
    const int qB = q0 + QT + t;
    const int c0 = ch * CCHUNK;

    const unsigned* q8b = g_q8 + (size_t)b * N_ * 16;
    const int* xxqb = g_xxq + b * N_;

    int* s_cxq = reinterpret_cast<int*>(smem + S_CXQ);
    int* s_fdA = reinterpret_cast<int*>(smem + S_FDA);
    int* s_fiA = reinterpret_cast<int*>(smem + S_FIA);
    int* s_fdB = reinterpret_cast<int*>(smem + S_FDB);
    int* s_fiB = reinterpret_cast<int*>(smem + S_FIB);
    const uint32_t fdA = sb + S_FDA + t * 4;
    const uint32_t fiA = sb + S_FIA + t * 4;
    const uint32_t fdB = sb + S_FDB + t * 4;
    const uint32_t fiB = sb + S_FIB + t * 4;

    // quantized query rows (2 x 16 words)
    unsigned qwA[16], qwB[16];
    {
        const uint4* pa = reinterpret_cast<const uint4*>(q8b + (size_t)qA * 16);
        const uint4* pb = reinterpret_cast<const uint4*>(q8b + (size_t)qB * 16);
#pragma unroll
        for (int i = 0; i < 4; ++i) {
            uint4 ua = pa[i], ub = pb[i];
            qwA[4 * i] = ua.x; qwA[4 * i + 1] = ua.y; qwA[4 * i + 2] = ua.z; qwA[4 * i + 3] = ua.w;
            qwB[4 * i] = ub.x; qwB[4 * i + 1] = ub.y; qwB[4 * i + 2] = ub.z; qwB[4 * i + 3] = ub.w;
        }
    }
    const int qxxqA = xxqb[qA];
    const int qxxqB = xxqb[qB];

    int mvA[M_KEEP], miA[M_KEEP], mvB[M_KEEP], miB[M_KEEP];
#pragma unroll
    for (int i = 0; i < M_KEEP; ++i) {
        mvA[i] = (int)0x80000000; miA[i] = 0;
        mvB[i] = (int)0x80000000; miB[i] = 0;
    }
    int thrA = (int)0x80000000, thrB = (int)0x80000000;
    int cntA = 0, cntB = 0;

    auto issue = [&](int tile, int buf) {
        const char* src = reinterpret_cast<const char*>(q8b + (size_t)(c0 + tile * CTILE) * 16);
        uint32_t dst = sb + S_T + buf * 8192;
        cp_async16(dst + t * 16, src + (size_t)t * 16);
        cp_async16(dst + (t + 256) * 16, src + (size_t)(t + 256) * 16);
        cp_commit();
        if (t < CTILE) s_cxq[buf * CTILE + t] = xxqb[c0 + tile * CTILE + t];
    };
    issue(0, 0);

    for (int tile = 0; tile < NT; ++tile) {
        const int buf = tile & 1;
        if (tile + 1 < NT) { issue(tile + 1, buf ^ 1); cp_wait1(); }
        else               { cp_wait0(); }
        __syncthreads();

        const uint4* tb = reinterpret_cast<const uint4*>(smem + S_T + buf * 8192);
        const int* cx = s_cxq + buf * CTILE;
        const int cbase = c0 + tile * CTILE;

#pragma unroll 1
        for (int jb = 0; jb < CTILE / 8; ++jb) {
            const int j0 = jb * 8;
            const uint4* rows = tb + j0 * 4;

            int accA[8], accB[8];
#pragma unroll
            for (int c = 0; c < 8; ++c) { accA[c] = 0; accB[c] = 0; }
#pragma unroll
            for (int i = 0; i < 4; ++i) {
#pragma unroll
                for (int c = 0; c < 8; ++c) {
                    uint4 u = rows[c * 4 + i];     // broadcast LDS.128 — shared by 2 queries
                    accA[c] = dp4a(accA[c], qwA[4 * i], u.x);
                    accA[c] = dp4a(accA[c], qwA[4 * i + 1], u.y);
                    accA[c] = dp4a(accA[c], qwA[4 * i + 2], u.z);
                    accA[c] = dp4a(accA[c], qwA[4 * i + 3], u.w);
                    accB[c] = dp4a(accB[c], qwB[4 * i], u.x);
                    accB[c] = dp4a(accB[c], qwB[4 * i + 1], u.y);
                    accB[c] = dp4a(accB[c], qwB[4 * i + 2], u.z);
                    accB[c] = dp4a(accB[c], qwB[4 * i + 3], u.w);
                }
            }

#pragma unroll
            for (int c = 0; c < 8; ++c) {
                int jj = cbase + j0 + c;
                int dvA = (accA[c] << 1) - qxxqA - cx[j0 + c];
                fifo_push(fdA, fiA, cntA, dvA, jj, thrA);
                cntA += (dvA > thrA) ? 1 : 0;
                int dvB = (accB[c] << 1) - qxxqB - cx[j0 + c];
                fifo_push(fdB, fiB, cntB, dvB, jj, thrB);
                cntB += (dvB > thrB) ? 1 : 0;
            }

            if (__any_sync(0xffffffffu, (cntA > F_ - 8) || (cntB > F_ - 8))) {
                int mA = (int)__reduce_max_sync(0xffffffffu, (unsigned)cntA);
#pragma unroll 1
                for (int e = 0; e < mA; ++e)
                    ins24(mvA, miA, s_fdA[e * QT + t], s_fiA[e * QT + t], e < cntA);
                int mB = (int)__reduce_max_sync(0xffffffffu, (unsigned)cntB);
#pragma unroll 1
                for (int e = 0; e < mB; ++e)
                    ins24(mvB, miB, s_fdB[e * QT + t], s_fiB[e * QT + t], e < cntB);
                thrA = mvA[M_KEEP - 1];
                thrB = mvB[M_KEEP - 1];
                cntA = 0;
                cntB = 0;
            }
        }
        __syncthreads();
    }

    // final flush
    {
        int mA = (int)__reduce_max_sync(0xffffffffu, (unsigned)cntA);
#pragma unroll 1
        for (int e = 0; e < mA; ++e)
            ins24(mvA, miA, s_fdA[e * QT + t], s_fiA[e * QT + t], e < cntA);
        int mB = (int)__reduce_max_sync(0xffffffffu, (unsigned)cntB);
#pragma unroll 1
        for (int e = 0; e < mB; ++e)
            ins24(mvB, miB, s_fdB[e * QT + t], s_fiB[e * QT + t], e < cntB);
    }

    // ---- exact fp32 rescore + sort + write, per query ----
    const float* fbf = g_feats + (size_t)b * N_ * C_;
    const float* xxb = g_xx + b * N_;
    const size_t L = (size_t)(b * CH + ch);

#pragma unroll 1
    for (int half = 0; half < 2; ++half) {
        const int q = half ? qB : qA;
        int* mi = half ? miB : miA;

        float fv[M_KEEP];
        {
            const u64* qp = reinterpret_cast<const u64*>(fbf + (size_t)q * C_);
            u64 qv2[32];
#pragma unroll
            for (int i = 0; i < 32; ++i) qv2[i] = qp[i];
            float qxxe = xxb[q];
#pragma unroll
            for (int i = 0; i < M_KEEP; ++i) {
                int idx = mi[i];
                const u64* cp = reinterpret_cast<const u64*>(fbf + (size_t)idx * C_);
                u64 a0 = 0, a1 = 0, a2 = 0, a3 = 0;
#pragma unroll
                for (int j = 0; j < 8; ++j) {
                    a0 = fma2(qv2[4 * j + 0], cp[4 * j + 0], a0);
                    a1 = fma2(qv2[4 * j + 1], cp[4 * j + 1], a1);
                    a2 = fma2(qv2[4 * j + 2], cp[4 * j + 2], a2);
                    a3 = fma2(qv2[4 * j + 3], cp[4 * j + 3], a3);
                }
                float inner = psum(add2(add2(a0, a1), add2(a2, a3)));
                fv[i] = 2.f * inner - qxxe - xxb[idx];
            }
        }

        // odd-even sort by (val desc, idx asc)
#pragma unroll
        for (int pass = 0; pass < M_KEEP; ++pass) {
#pragma unroll
            for (int i = (pass & 1); i + 1 < M_KEEP; i += 2) {
                bool sw = (fv[i + 1] > fv[i]) || (fv[i + 1] == fv[i] && mi[i + 1] < mi[i]);
                float tv = sw ? fv[i + 1] : fv[i];
                fv[i + 1] = sw ? fv[i] : fv[i + 1];
                fv[i] = tv;
                int ti = sw ? mi[i + 1] : mi[i];
                mi[i + 1] = sw ? mi[i] : mi[i + 1];
                mi[i] = ti;
            }
        }

        float* pv = g_pval + (L * N_ + q) * M_KEEP;
        int*   pi = g_pidx + (L * N_ + q) * M_KEEP;
#pragma unroll
        for (int i = 0; i < M_KEEP; ++i) { pv[i] = fv[i]; pi[i] = mi[i]; }
    }
}

// ---------------- kernel 2b: CH-way merge of partial top lists ----------------
__global__ void __launch_bounds__(256) merge_kernel() {
    int id = blockIdx.x * 256 + threadIdx.x;       // 0 .. B*N-1
    int b = id >> 13;
    int q = id & (N_ - 1);

    const float* pv[CH];
    const int*   pi[CH];
    float hv[CH];
    int   hx[CH];
    int   cur[CH];
#pragma unroll
    for (int c = 0; c < CH; ++c) {
        pv[c] = g_pval + (((size_t)(b * CH + c)) * N_ + q) * M_KEEP;
        pi[c] = g_pidx + (((size_t)(b * CH + c)) * N_ + q) * M_KEEP;
        hv[c] = pv[c][0];
        hx[c] = pi[c][0];
        cur[c] = 0;
    }
    int* og = g_knn + (size_t)id * K_;
#pragma unroll
    for (int s = 0; s < 16; ++s) {
        int best = 0;
#pragma unroll
        for (int c = 1; c < CH; ++c)
            if (hv[c] > hv[best] || (hv[c] == hv[best] && hx[c] < hx[best])) best = c;
        og[s] = hx[best];
        if (++cur[best] < M_KEEP) {
            hv[best] = pv[best][cur[best]];
            hx[best] = pi[best][cur[best]];
        } else {
            hv[best] = -3.4e38f;
            hx[best] = 0x7fffffff;
        }
    }
}

// ---------------- kernel 3a: per-point GEMM  Y = W2.x, Z = (W1-W2).x ----------------
// smem-staged point tile; 128 threads = channels, 64 points per CTA.
__global__ void __launch_bounds__(128) zy_kernel(const float* __restrict__ W) {
    __shared__ __align__(16) float s_x[64 * C_];    // 16 KB point tile
    const int t = threadIdx.x;                      // channel
    const int b = blockIdx.y;
    const int p0 = blockIdx.x * 64;

    // stage tile: 1024 16B chunks, 8 per thread (coalesced)
    {
        uint32_t dst = smem_u32(s_x);
        const char* src = reinterpret_cast<const char*>(g_feats + ((size_t)b * N_ + p0) * C_);
#pragma unroll
        for (int i = 0; i < 8; ++i) {
            int c = t + i * 128;
            cp_async16(dst + (uint32_t)c * 16, src + (size_t)c * 16);
        }
        cp_commit();
    }

    // w2r = W2 row; wzr = (W1 - W2) row, packed f32x2
    u64 w2r[32], wzr[32];
    {
        const u64* wp = reinterpret_cast<const u64*>(W + (size_t)t * 2 * C_);
        const u64 neg1 = dup2(-1.f);
#pragma unroll
        for (int i = 0; i < 32; ++i) {
            u64 w1 = wp[i];
            u64 w2 = wp[32 + i];
            w2r[i] = w2;
            wzr[i] = fma2(w2, neg1, w1);            // w1 - w2 (exact)
        }
    }

    float* Yb = g_Y + ((size_t)b * N_ + p0) * O_;
    float* Zb = g_Z + ((size_t)b * N_ + p0) * O_;

    cp_wait0();
    __syncthreads();

#pragma unroll 1
    for (int pl = 0; pl < 64; ++pl) {
        const ulonglong2* xp = reinterpret_cast<const ulonglong2*>(s_x + pl * C_);
        u64 y0 = 0, y1 = 0, y2 = 0, y3 = 0;
        u64 z0 = 0, z1 = 0, z2 = 0, z3 = 0;
#pragma unroll
        for (int i = 0; i < 8; ++i) {
            ulonglong2 ua = xp[2 * i];
            ulonglong2 ub = xp[2 * i + 1];
            y0 = fma2(w2r[4 * i + 0], ua.x, y0);
            y1 = fma2(w2r[4 * i + 1], ua.y, y1);
            y2 = fma2(w2r[4 * i + 2], ub.x, y2);
            y3 = fma2(w2r[4 * i + 3], ub.y, y3);
            z0 = fma2(wzr[4 * i + 0], ua.x, z0);
            z1 = fma2(wzr[4 * i + 1], ua.y, z1);
            z2 = fma2(wzr[4 * i + 2], ub.x, z2);
            z3 = fma2(wzr[4 * i + 3], ub.y, z3);
        }
        Yb[pl * O_ + t] = psum(add2(add2(y0, y1), add2(y2, y3)));
        Zb[pl * O_ + t] = psum(add2(add2(z0, z1), add2(z2, z3)));
    }
}

// ---------------- kernel 3b: gather-max epilogue ----------------
#define GPB 64
__global__ void __launch_bounds__(128) gmax_kernel(const float* __restrict__ bias,
                                                   float* __restrict__ out) {
    __shared__ int   s_nidx[GPB * K_];
    __shared__ float s_res[128 * 65];

    const int t = threadIdx.x;                      // channel
    const int b = blockIdx.y;
    const int p0 = blockIdx.x * GPB;

    const float* Yb = g_Y + (size_t)b * N_ * O_;
    const float* Zb = g_Z + (size_t)b * N_ * O_;
    const float bo = bias[t];

    for (int i = t; i < GPB * K_; i += 128)
        s_nidx[i] = g_knn[(size_t)(b * N_ + p0) * K_ + i];
    __syncthreads();

#pragma unroll 1
    for (int pl = 0; pl < GPB; ++pl) {
        const int* nn = s_nidx + pl * K_;
        float m = -3.4e38f;
#pragma unroll
        for (int k = 0; k < K_; ++k)
            m = fmaxf(m, Yb[(size_t)nn[k] * O_ + t]);
        float z = Zb[(size_t)(p0 + pl) * O_ + t];
        s_res[t * 65 + pl] = z + m + bo;
    }
    __syncthreads();

#pragma unroll
    for (int i = 0; i < 64; ++i) {
        int idx = t + i * 128;
        int o = idx >> 6;
        int p = idx & 63;
        out[((size_t)(b * O_ + o)) * N_ + p0 + p] = s_res[o * 65 + p];
    }
}

// ---------------- launch ----------------
extern "C" void kernel_launch(void* const* d_in, const int* in_sizes, int n_in,
                              void* d_out, int out_size) {
    (void)in_sizes; (void)n_in; (void)out_size;
    const float* x    = (const float*)d_in[0];   // (4, 64, 8192, 1)
    const float* W    = (const float*)d_in[1];   // (128, 128)
    const float* bias = (const float*)d_in[2];   // (128,)
    float* out = (float*)d_out;                  // (4, 128, 8192, 1)

    cudaFuncSetAttribute(knn_kernel, cudaFuncAttributeMaxDynamicSharedMemorySize, KNN_SMEM);

    prep_kernel<<<(B_ * N_) / 256, 256>>>(x);
    knn_kernel<<<dim3(N_ / (QT * QP), CH, B_), QT, KNN_SMEM>>>();
    merge_kernel<<<(B_ * N_) / 256, 256>>>();
    zy_kernel<<<dim3(N_ / 64, B_), 128>>>(W);
    gmax_kernel<<<dim3(N_ / GPB, B_), 128>>>(bias, out);
}

// round 14
// speedup vs baseline: 2.7919x; 1.1457x over previous
#include <cuda_runtime.h>
#include <cstdint>

#define B_ 4
#define N_ 8192
#define C_ 64
#define K_ 16
#define O_ 128

#define NTILE 64                   // candidates per tile
#define NT2 (N_ / NTILE)           // 128 tiles
#define M_KEEP 20                  // filter margin (>=16)
#define F_ 12                      // FIFO slots per lane
#define NL 2                       // partial lists per query (column halves)
#define QS 20.0f                   // int8 quantization scale

// ---------------- scratch (no allocs allowed) ----------------
__device__ __align__(16) float    g_feats[B_ * N_ * C_];
__device__ __align__(16) float    g_xx[B_ * N_];
__device__ __align__(16) unsigned g_q8[B_ * N_ * 16];     // packed int8 feats (4/word)
__device__ __align__(16) int      g_xxq[B_ * N_];         // quantized sq norms
__device__ __align__(16) int      g_knn[B_ * N_ * K_];
__device__ __align__(16) float    g_pval[B_ * NL * N_ * M_KEEP];
__device__ __align__(16) int      g_pidx[B_ * NL * N_ * M_KEEP];
__device__ __align__(16) float    g_Y[B_ * N_ * O_];      // W2 . x_n
__device__ __align__(16) float    g_Z[B_ * N_ * O_];      // (W1-W2) . x_n

typedef unsigned long long u64;

// ---------------- packed f32x2 helpers (sm_103a) ----------------
__device__ __forceinline__ u64 fma2(u64 a, u64 b, u64 c) {
    u64 d;
    asm("fma.rn.f32x2 %0, %1, %2, %3;" : "=l"(d) : "l"(a), "l"(b), "l"(c));
    return d;
}
__device__ __forceinline__ u64 add2(u64 a, u64 b) {
    u64 d;
    asm("add.rn.f32x2 %0, %1, %2;" : "=l"(d) : "l"(a), "l"(b));
    return d;
}
__device__ __forceinline__ u64 dup2(float a) {
    u64 d;
    asm("mov.b64 %0, {%1, %1};" : "=l"(d) : "f"(a));
    return d;
}
__device__ __forceinline__ float psum(u64 v) {
    return __uint_as_float((unsigned)v) + __uint_as_float((unsigned)(v >> 32));
}
__device__ __forceinline__ uint32_t smem_u32(const void* p) {
    uint32_t a;
    asm("{ .reg .u64 t; cvta.to.shared.u64 t, %1; cvt.u32.u64 %0, t; }" : "=r"(a) : "l"(p));
    return a;
}
__device__ __forceinline__ void cp_async16(uint32_t dst, const void* src) {
    asm volatile("cp.async.cg.shared.global [%0], [%1], 16;" :: "r"(dst), "l"(src) : "memory");
}
__device__ __forceinline__ void cp_commit() {
    asm volatile("cp.async.commit_group;" ::: "memory");
}
__device__ __forceinline__ void cp_wait1() {
    asm volatile("cp.async.wait_group 1;" ::: "memory");
}
__device__ __forceinline__ void cp_wait0() {
    asm volatile("cp.async.wait_group 0;" ::: "memory");
}

// int8 tensor-core MMA (baseline PTX, legal on compute_103): D += A(16x32) B(32x8)
__device__ __forceinline__ void imma(int* c, const unsigned* a, const unsigned* b) {
    asm volatile(
        "mma.sync.aligned.m16n8k32.row.col.s32.s8.s8.s32 "
        "{%0,%1,%2,%3}, {%4,%5,%6,%7}, {%8,%9}, {%0,%1,%2,%3};"
        : "+r"(c[0]), "+r"(c[1]), "+r"(c[2]), "+r"(c[3])
        : "r"(a[0]), "r"(a[1]), "r"(a[2]), "r"(a[3]), "r"(b[0]), "r"(b[1]));
}

// predicated FIFO push (proven R13)
__device__ __forceinline__ void fifo_push(uint32_t fd_base, uint32_t fi_base,
                                          int cnt, int dv, int jj, int thr) {
    uint32_t off = (uint32_t)cnt << 10;    // cnt * 256 * 4
    asm volatile(
        "{\n\t.reg .pred p;\n\t"
        "setp.gt.s32 p, %0, %1;\n\t"
        "@p st.shared.b32 [%2], %0;\n\t"
        "@p st.shared.b32 [%3], %4;\n\t}"
        :: "r"(dv), "r"(thr), "r"(fd_base + off), "r"(fi_base + off), "r"(jj)
        : "memory");
}

// branch-free insert into descending sorted reg arrays (M_KEEP slots).
__device__ __forceinline__ void insM(int* mv, int* mi, int dv, int jj, bool live) {
    bool c[M_KEEP];
#pragma unroll
    for (int i = 0; i < M_KEEP; ++i) c[i] = live && (mv[i] < dv);
#pragma unroll
    for (int i = M_KEEP - 1; i >= 1; --i) {
        mv[i] = c[i - 1] ? mv[i - 1] : (c[i] ? dv : mv[i]);
        mi[i] = c[i - 1] ? mi[i - 1] : (c[i] ? jj : mi[i]);
    }
    mv[0] = c[0] ? dv : mv[0];
    mi[0] = c[0] ? jj : mi[0];
}

// ---------------- kernel 1: transpose, norms, int8 quantize ----------------
__global__ void __launch_bounds__(256) prep_kernel(const float* __restrict__ x) {
    int idx = blockIdx.x * 256 + threadIdx.x;      // 0 .. B*N-1
    int b = idx >> 13;
    int n = idx & (N_ - 1);
    const float* xb = x + (size_t)b * C_ * N_ + n;
    float v[C_];
    float acc = 0.f;
#pragma unroll
    for (int c = 0; c < C_; ++c) {
        float t = xb[(size_t)c * N_];              // coalesced across threads
        v[c] = t;
        acc = fmaf(t, t, acc);
    }
    float4* fp = reinterpret_cast<float4*>(g_feats + (size_t)idx * C_);
#pragma unroll
    for (int i = 0; i < C_ / 4; ++i)
        fp[i] = make_float4(v[4 * i], v[4 * i + 1], v[4 * i + 2], v[4 * i + 3]);

    unsigned pk[16];
    int xxq = 0;
#pragma unroll
    for (int g = 0; g < 16; ++g) {
        unsigned p = 0;
#pragma unroll
        for (int e = 0; e < 4; ++e) {
            float s = fminf(fmaxf(v[4 * g + e] * QS, -127.f), 127.f);
            int qi = __float2int_rn(s);
            xxq += qi * qi;
            p |= ((unsigned)qi & 0xFFu) << (8 * e);
        }
        pk[g] = p;
    }
    uint4* qp = reinterpret_cast<uint4*>(g_q8 + (size_t)idx * 16);
#pragma unroll
    for (int i = 0; i < 4; ++i)
        qp[i] = make_uint4(pk[4 * i], pk[4 * i + 1], pk[4 * i + 2], pk[4 * i + 3]);

    g_xxq[idx] = xxq;
    g_xx[idx] = acc;
}

// ---------------- kernel 2: imma KNN filter + exact fp32 rescore ----------------
// Grid (N/128, B_) = 256 CTAs, 256 threads, occ 2. CTA: 128 queries x all 8192 cands.
// Warp (w&3 -> 32-query rows, w>>2 -> 32-cand cols). 64-cand tiles, double-buffered.
// smem layout (bytes):
#define S_A    0                          // A int8 tile 128x64 = 8192
#define S_B    8192                       // 2 x 4096 cand tiles
#define S_CXQ  16384                      // 2 x 64 ints
#define S_DIST 16896                      // 128 x 66 ints = 33792
#define S_FD   50688                      // F_ x 256 ints
#define S_FI   62976                      // F_ x 256 ints
#define KNN_SMEM 75264

__global__ void __launch_bounds__(256, 2) knn_kernel() {
    extern __shared__ char smem[];
    uint32_t sb = smem_u32(smem);
    const int t = threadIdx.x;
    const int w = t >> 5;
    const int l = t & 31;
    const int gid = l >> 2;                // 0..7
    const int tig = l & 3;                 // 0..3
    const int b = blockIdx.y;
    const int q0 = blockIdx.x * 128;

    const int m0 = (w & 3) * 32;           // warp query-row base
    const int n0 = (w >> 2) * 32;          // warp cand-col base

    const unsigned* q8b = g_q8 + (size_t)b * N_ * 16;
    const int* xxqb = g_xxq + b * N_;

    int* s_cxq = reinterpret_cast<int*>(smem + S_CXQ);
    int* s_fd  = reinterpret_cast<int*>(smem + S_FD);
    int* s_fi  = reinterpret_cast<int*>(smem + S_FI);
    const uint32_t fd = sb + S_FD + t * 4;
    const uint32_t fi = sb + S_FI + t * 4;

    // ---- A tile load (once): 128 rows x 64B = 512 chunks ----
    {
        const char* asrc = reinterpret_cast<const char*>(q8b + (size_t)q0 * 16);
        cp_async16(sb + S_A + (uint32_t)t * 16, asrc + (size_t)t * 16);
        cp_async16(sb + S_A + (uint32_t)(t + 256) * 16, asrc + (size_t)(t + 256) * 16);
    }
    // ---- B tile loader: 64 rows x 64B = 256 chunks, 1 per thread ----
    auto issueB = [&](int tile, int buf) {
        const char* src = reinterpret_cast<const char*>(q8b + (size_t)(tile * NTILE) * 16);
        cp_async16(sb + S_B + buf * 4096 + (uint32_t)t * 16, src + (size_t)t * 16);
        cp_commit();
        if (t < NTILE) s_cxq[buf * NTILE + t] = xxqb[tile * NTILE + t];
    };
    issueB(0, 0);

    // per-thread query norms: rows m0 + mf*16 + gid (+8)
    int qn[4];
#pragma unroll
    for (int mf = 0; mf < 2; ++mf) {
        qn[mf * 2] = xxqb[q0 + m0 + mf * 16 + gid];
        qn[mf * 2 + 1] = xxqb[q0 + m0 + mf * 16 + gid + 8];
    }

    int mv[M_KEEP], mi[M_KEEP];
#pragma unroll
    for (int i = 0; i < M_KEEP; ++i) { mv[i] = (int)0x80000000; mi[i] = 0; }
    int thr = (int)0x80000000;
    int cnt = 0;

    cp_wait0();
    __syncthreads();                        // A + B[0] + cxq[0] visible

    // ---- persistent A fragments: af[mf][ks][4] ----
    unsigned af[2][2][4];
#pragma unroll
    for (int mf = 0; mf < 2; ++mf)
#pragma unroll
        for (int ks = 0; ks < 2; ++ks) {
            const char* ab = smem + S_A + (m0 + mf * 16 + gid) * 64 + ks * 32 + tig * 4;
            af[mf][ks][0] = *reinterpret_cast<const unsigned*>(ab);
            af[mf][ks][1] = *reinterpret_cast<const unsigned*>(ab + 512);   // row +8
            af[mf][ks][2] = *reinterpret_cast<const unsigned*>(ab + 16);    // k +16
            af[mf][ks][3] = *reinterpret_cast<const unsigned*>(ab + 512 + 16);
        }

    const int srow = t & 127;               // scan: query row
    const int shalf = t >> 7;               // scan: column half (32 cols)
    int* dist = reinterpret_cast<int*>(smem + S_DIST);

    for (int tile = 0; tile < NT2; ++tile) {
        const int buf = tile & 1;
        if (tile + 1 < NT2) { issueB(tile + 1, buf ^ 1); cp_wait1(); }
        else                { cp_wait0(); }
        __syncthreads();                    // B(tile)+cxq ready; prev scan done (dist free)

        // ---- MMA: 2mf x 4nf x 2ks = 16 imma ----
        const char* Bt = smem + S_B + buf * 4096;
        int acc[2][4][4];
#pragma unroll
        for (int mf = 0; mf < 2; ++mf)
#pragma unroll
            for (int nf = 0; nf < 4; ++nf)
#pragma unroll
                for (int r = 0; r < 4; ++r) acc[mf][nf][r] = 0;

#pragma unroll
        for (int ks = 0; ks < 2; ++ks) {
            unsigned bf[4][2];
#pragma unroll
            for (int nf = 0; nf < 4; ++nf) {
                const char* bb = Bt + (n0 + nf * 8 + gid) * 64 + ks * 32 + tig * 4;
                bf[nf][0] = *reinterpret_cast<const unsigned*>(bb);
                bf[nf][1] = *reinterpret_cast<const unsigned*>(bb + 16);
            }
#pragma unroll
            for (int mf = 0; mf < 2; ++mf)
#pragma unroll
                for (int nf = 0; nf < 4; ++nf)
                    imma(acc[mf][nf], af[mf][ks], bf[nf]);
        }

        // ---- fold: d = 2*acc - qxx - cxx -> dist tile (stride 66 ints) ----
#pragma unroll
        for (int nf = 0; nf < 4; ++nf) {
            int col = n0 + nf * 8 + tig * 2;
            int2 cx2 = *reinterpret_cast<const int2*>(s_cxq + buf * NTILE + col);
#pragma unroll
            for (int mf = 0; mf < 2; ++mf) {
                int row = m0 + mf * 16 + gid;
                int2 dlo, dhi;
                dlo.x = (acc[mf][nf][0] << 1) - qn[mf * 2] - cx2.x;
                dlo.y = (acc[mf][nf][1] << 1) - qn[mf * 2] - cx2.y;
                dhi.x = (acc[mf][nf][2] << 1) - qn[mf * 2 + 1] - cx2.x;
                dhi.y = (acc[mf][nf][3] << 1) - qn[mf * 2 + 1] - cx2.y;
                *reinterpret_cast<int2*>(dist + row * 66 + col) = dlo;
                *reinterpret_cast<int2*>(dist + (row + 8) * 66 + col) = dhi;
            }
        }
        __syncthreads();                    // dist complete

        // ---- scan: thread owns (srow, 32-col half), batches of 8 ----
        {
            const int2* base2 = reinterpret_cast<const int2*>(dist + srow * 66 + shalf * 32);
            const int cbase = tile * NTILE + shalf * 32;
#pragma unroll 1
            for (int jb = 0; jb < 4; ++jb) {
                int2 v0 = base2[jb * 4 + 0];
                int2 v1 = base2[jb * 4 + 1];
                int2 v2 = base2[jb * 4 + 2];
                int2 v3 = base2[jb * 4 + 3];
                int d[8] = { v0.x, v0.y, v1.x, v1.y, v2.x, v2.y, v3.x, v3.y };
#pragma unroll
                for (int e = 0; e < 8; ++e) {
                    fifo_push(fd, fi, cnt, d[e], cbase + jb * 8 + e, thr);
                    cnt += (d[e] > thr) ? 1 : 0;
                }
                if (__any_sync(0xffffffffu, cnt > F_ - 8)) {
                    int m = (int)__reduce_max_sync(0xffffffffu, (unsigned)cnt);
#pragma unroll 1
                    for (int e = 0; e < m; ++e)
                        insM(mv, mi, s_fd[e * 256 + t], s_fi[e * 256 + t], e < cnt);
                    thr = mv[M_KEEP - 1];
                    cnt = 0;
                }
            }
        }
        // loop-top __syncthreads separates this scan from next fold
    }

    // final flush
    {
        int m = (int)__reduce_max_sync(0xffffffffu, (unsigned)cnt);
#pragma unroll 1
        for (int e = 0; e < m; ++e)
            insM(mv, mi, s_fd[e * 256 + t], s_fi[e * 256 + t], e < cnt);
    }

    // ---- exact fp32 rescore (proven path) ----
    const int q = q0 + srow;
    float fv[M_KEEP];
    {
        const float* fbf = g_feats + (size_t)b * N_ * C_;
        const float* xxb = g_xx + b * N_;
        const u64* qp = reinterpret_cast<const u64*>(fbf + (size_t)q * C_);
        u64 qv2[32];
#pragma unroll
        for (int i = 0; i < 32; ++i) qv2[i] = qp[i];
        float qxxe = xxb[q];
#pragma unroll
        for (int i = 0; i < M_KEEP; ++i) {
            int idx = mi[i];
            const u64* cp = reinterpret_cast<const u64*>(fbf + (size_t)idx * C_);
            u64 a0 = 0, a1 = 0, a2 = 0, a3 = 0;
#pragma unroll
            for (int j = 0; j < 8; ++j) {
                a0 = fma2(qv2[4 * j + 0], cp[4 * j + 0], a0);
                a1 = fma2(qv2[4 * j + 1], cp[4 * j + 1], a1);
                a2 = fma2(qv2[4 * j + 2], cp[4 * j + 2], a2);
                a3 = fma2(qv2[4 * j + 3], cp[4 * j + 3], a3);
            }
            float inner = psum(add2(add2(a0, a1), add2(a2, a3)));
            fv[i] = 2.f * inner - qxxe - xxb[idx];
        }
    }

    // odd-even sort by (val desc, idx asc)
#pragma unroll
    for (int pass = 0; pass < M_KEEP; ++pass) {
#pragma unroll
        for (int i = (pass & 1); i + 1 < M_KEEP; i += 2) {
            bool sw = (fv[i + 1] > fv[i]) || (fv[i + 1] == fv[i] && mi[i + 1] < mi[i]);
            float tv = sw ? fv[i + 1] : fv[i];
            fv[i + 1] = sw ? fv[i] : fv[i + 1];
            fv[i] = tv;
            int ti = sw ? mi[i + 1] : mi[i];
            mi[i + 1] = sw ? mi[i] : mi[i + 1];
            mi[i] = ti;
        }
    }

    // write partial list (list id = b*NL + shalf)
    {
        size_t L = (size_t)(b * NL + shalf);
        float* pv = g_pval + (L * N_ + q) * M_KEEP;
        int*   pi = g_pidx + (L * N_ + q) * M_KEEP;
#pragma unroll
        for (int i = 0; i < M_KEEP; ++i) { pv[i] = fv[i]; pi[i] = mi[i]; }
    }
}

// ---------------- kernel 2b: NL-way merge of partial top lists ----------------
__global__ void __launch_bounds__(256) merge_kernel() {
    int id = blockIdx.x * 256 + threadIdx.x;       // 0 .. B*N-1
    int b = id >> 13;
    int q = id & (N_ - 1);

    const float* pv[NL];
    const int*   pi[NL];
    float hv[NL];
    int   hx[NL];
    int   cur[NL];
#pragma unroll
    for (int c = 0; c < NL; ++c) {
        pv[c] = g_pval + (((size_t)(b * NL + c)) * N_ + q) * M_KEEP;
        pi[c] = g_pidx + (((size_t)(b * NL + c)) * N_ + q) * M_KEEP;
        hv[c] = pv[c][0];
        hx[c] = pi[c][0];
        cur[c] = 0;
    }
    int* og = g_knn + (size_t)id * K_;
#pragma unroll
    for (int s = 0; s < 16; ++s) {
        int best = 0;
#pragma unroll
        for (int c = 1; c < NL; ++c)
            if (hv[c] > hv[best] || (hv[c] == hv[best] && hx[c] < hx[best])) best = c;
        og[s] = hx[best];
        if (++cur[best] < M_KEEP) {
            hv[best] = pv[best][cur[best]];
            hx[best] = pi[best][cur[best]];
        } else {
            hv[best] = -3.4e38f;
            hx[best] = 0x7fffffff;
        }
    }
}

// ---------------- kernel 3a: per-point GEMM  Y = W2.x, Z = (W1-W2).x ----------------
__global__ void __launch_bounds__(128) zy_kernel(const float* __restrict__ W) {
    __shared__ __align__(16) float s_x[64 * C_];    // 16 KB point tile
    const int t = threadIdx.x;                      // channel
    const int b = blockIdx.y;
    const int p0 = blockIdx.x * 64;

    {
        uint32_t dst = smem_u32(s_x);
        const char* src = reinterpret_cast<const char*>(g_feats + ((size_t)b * N_ + p0) * C_);
#pragma unroll
        for (int i = 0; i < 8; ++i) {
            int c = t + i * 128;
            cp_async16(dst + (uint32_t)c * 16, src + (size_t)c * 16);
        }
        cp_commit();
    }

    u64 w2r[32], wzr[32];
    {
        const u64* wp = reinterpret_cast<const u64*>(W + (size_t)t * 2 * C_);
        const u64 neg1 = dup2(-1.f);
#pragma unroll
        for (int i = 0; i < 32; ++i) {
            u64 w1 = wp[i];
            u64 w2 = wp[32 + i];
            w2r[i] = w2;
            wzr[i] = fma2(w2, neg1, w1);            // w1 - w2 (exact)
        }
    }

    float* Yb = g_Y + ((size_t)b * N_ + p0) * O_;
    float* Zb = g_Z + ((size_t)b * N_ + p0) * O_;

    cp_wait0();
    __syncthreads();

#pragma unroll 1
    for (int pl = 0; pl < 64; ++pl) {
        const ulonglong2* xp = reinterpret_cast<const ulonglong2*>(s_x + pl * C_);
        u64 y0 = 0, y1 = 0, y2 = 0, y3 = 0;
        u64 z0 = 0, z1 = 0, z2 = 0, z3 = 0;
#pragma unroll
        for (int i = 0; i < 8; ++i) {
            ulonglong2 ua = xp[2 * i];
            ulonglong2 ub = xp[2 * i + 1];
            y0 = fma2(w2r[4 * i + 0], ua.x, y0);
            y1 = fma2(w2r[4 * i + 1], ua.y, y1);
            y2 = fma2(w2r[4 * i + 2], ub.x, y2);
            y3 = fma2(w2r[4 * i + 3], ub.y, y3);
            z0 = fma2(wzr[4 * i + 0], ua.x, z0);
            z1 = fma2(wzr[4 * i + 1], ua.y, z1);
            z2 = fma2(wzr[4 * i + 2], ub.x, z2);
            z3 = fma2(wzr[4 * i + 3], ub.y, z3);
        }
        Yb[pl * O_ + t] = psum(add2(add2(y0, y1), add2(y2, y3)));
        Zb[pl * O_ + t] = psum(add2(add2(z0, z1), add2(z2, z3)));
    }
}

// ---------------- kernel 3b: gather-max epilogue ----------------
#define GPB 64
__global__ void __launch_bounds__(128) gmax_kernel(const float* __restrict__ bias,
                                                   float* __restrict__ out) {
    __shared__ int   s_nidx[GPB * K_];
    __shared__ float s_res[128 * 65];

    const int t = threadIdx.x;                      // channel
    const int b = blockIdx.y;
    const int p0 = blockIdx.x * GPB;

    const float* Yb = g_Y + (size_t)b * N_ * O_;
    const float* Zb = g_Z + (size_t)b * N_ * O_;
    const float bo = bias[t];

    for (int i = t; i < GPB * K_; i += 128)
        s_nidx[i] = g_knn[(size_t)(b * N_ + p0) * K_ + i];
    __syncthreads();

#pragma unroll 1
    for (int pl = 0; pl < GPB; ++pl) {
        const int* nn = s_nidx + pl * K_;
        float m = -3.4e38f;
#pragma unroll
        for (int k = 0; k < K_; ++k)
            m = fmaxf(m, Yb[(size_t)nn[k] * O_ + t]);
        float z = Zb[(size_t)(p0 + pl) * O_ + t];
        s_res[t * 65 + pl] = z + m + bo;
    }
    __syncthreads();

#pragma unroll
    for (int i = 0; i < 64; ++i) {
        int idx = t + i * 128;
        int o = idx >> 6;
        int p = idx & 63;
        out[((size_t)(b * O_ + o)) * N_ + p0 + p] = s_res[o * 65 + p];
    }
}

// ---------------- launch ----------------
extern "C" void kernel_launch(void* const* d_in, const int* in_sizes, int n_in,
                              void* d_out, int out_size) {
    (void)in_sizes; (void)n_in; (void)out_size;
    const float* x    = (const float*)d_in[0];   // (4, 64, 8192, 1)
    const float* W    = (const float*)d_in[1];   // (128, 128)
    const float* bias = (const float*)d_in[2];   // (128,)
    float* out = (float*)d_out;                  // (4, 128, 8192, 1)

    cudaFuncSetAttribute(knn_kernel, cudaFuncAttributeMaxDynamicSharedMemorySize, KNN_SMEM);

    prep_kernel<<<(B_ * N_) / 256, 256>>>(x);
    knn_kernel<<<dim3(N_ / 128, B_), 256, KNN_SMEM>>>();
    merge_kernel<<<(B_ * N_) / 256, 256>>>();
    zy_kernel<<<dim3(N_ / 64, B_), 128>>>(W);
    gmax_kernel<<<dim3(N_ / GPB, B_), 128>>>(bias, out);
}

// round 15
// speedup vs baseline: 2.9314x; 1.0499x over previous
#include <cuda_runtime.h>
#include <cstdint>

#define B_ 4
#define N_ 8192
#define C_ 64
#define K_ 16
#define O_ 128

#define NTILE 64                   // candidates per tile
#define NT2 (N_ / NTILE)           // 128 tiles
#define M_KEEP 20                  // filter margin (>=16)
#define F_ 12                      // FIFO slots per lane
#define NL 2                       // partial lists per query (column halves)
#define QS 20.0f                   // int8 quantization scale

// ---------------- scratch (no allocs allowed) ----------------
__device__ __align__(16) float    g_feats[B_ * N_ * C_];
__device__ __align__(16) float    g_xx[B_ * N_];
__device__ __align__(16) unsigned g_q8[B_ * N_ * 16];     // packed int8 feats (4/word)
__device__ __align__(16) int      g_xxq[B_ * N_];         // quantized sq norms
__device__ __align__(16) int      g_knn[B_ * N_ * K_];
__device__ __align__(16) float    g_pval[B_ * NL * N_ * M_KEEP];
__device__ __align__(16) int      g_pidx[B_ * NL * N_ * M_KEEP];
__device__ __align__(16) float    g_Y[B_ * N_ * O_];      // W2 . x_n
__device__ __align__(16) float    g_Z[B_ * N_ * O_];      // (W1-W2) . x_n

typedef unsigned long long u64;

// ---------------- packed f32x2 helpers (sm_103a) ----------------
__device__ __forceinline__ u64 fma2(u64 a, u64 b, u64 c) {
    u64 d;
    asm("fma.rn.f32x2 %0, %1, %2, %3;" : "=l"(d) : "l"(a), "l"(b), "l"(c));
    return d;
}
__device__ __forceinline__ u64 add2(u64 a, u64 b) {
    u64 d;
    asm("add.rn.f32x2 %0, %1, %2;" : "=l"(d) : "l"(a), "l"(b));
    return d;
}
__device__ __forceinline__ u64 dup2(float a) {
    u64 d;
    asm("mov.b64 %0, {%1, %1};" : "=l"(d) : "f"(a));
    return d;
}
__device__ __forceinline__ float psum(u64 v) {
    return __uint_as_float((unsigned)v) + __uint_as_float((unsigned)(v >> 32));
}
__device__ __forceinline__ uint32_t smem_u32(const void* p) {
    uint32_t a;
    asm("{ .reg .u64 t; cvta.to.shared.u64 t, %1; cvt.u32.u64 %0, t; }" : "=r"(a) : "l"(p));
    return a;
}
__device__ __forceinline__ void cp_async16(uint32_t dst, const void* src) {
    asm volatile("cp.async.cg.shared.global [%0], [%1], 16;" :: "r"(dst), "l"(src) : "memory");
}
__device__ __forceinline__ void cp_commit() {
    asm volatile("cp.async.commit_group;" ::: "memory");
}
__device__ __forceinline__ void cp_wait1() {
    asm volatile("cp.async.wait_group 1;" ::: "memory");
}
__device__ __forceinline__ void cp_wait0() {
    asm volatile("cp.async.wait_group 0;" ::: "memory");
}

// int8 tensor-core MMA (baseline PTX, legal on compute_103): D += A(16x32) B(32x8)
__device__ __forceinline__ void imma(int* c, const unsigned* a, const unsigned* b) {
    asm volatile(
        "mma.sync.aligned.m16n8k32.row.col.s32.s8.s8.s32 "
        "{%0,%1,%2,%3}, {%4,%5,%6,%7}, {%8,%9}, {%0,%1,%2,%3};"
        : "+r"(c[0]), "+r"(c[1]), "+r"(c[2]), "+r"(c[3])
        : "r"(a[0]), "r"(a[1]), "r"(a[2]), "r"(a[3]), "r"(b[0]), "r"(b[1]));
}

// predicated FIFO push (proven R13)
__device__ __forceinline__ void fifo_push(uint32_t fd_base, uint32_t fi_base,
                                          int cnt, int dv, int jj, int thr) {
    uint32_t off = (uint32_t)cnt << 10;    // cnt * 256 * 4
    asm volatile(
        "{\n\t.reg .pred p;\n\t"
        "setp.gt.s32 p, %0, %1;\n\t"
        "@p st.shared.b32 [%2], %0;\n\t"
        "@p st.shared.b32 [%3], %4;\n\t}"
        :: "r"(dv), "r"(thr), "r"(fd_base + off), "r"(fi_base + off), "r"(jj)
        : "memory");
}

// branch-free insert into descending sorted reg arrays (M_KEEP slots).
__device__ __forceinline__ void insM(int* mv, int* mi, int dv, int jj, bool live) {
    bool c[M_KEEP];
#pragma unroll
    for (int i = 0; i < M_KEEP; ++i) c[i] = live && (mv[i] < dv);
#pragma unroll
    for (int i = M_KEEP - 1; i >= 1; --i) {
        mv[i] = c[i - 1] ? mv[i - 1] : (c[i] ? dv : mv[i]);
        mi[i] = c[i - 1] ? mi[i - 1] : (c[i] ? jj : mi[i]);
    }
    mv[0] = c[0] ? dv : mv[0];
    mi[0] = c[0] ? jj : mi[0];
}

// ---------------- kernel 1: transpose, norms, int8 quantize ----------------
__global__ void __launch_bounds__(256) prep_kernel(const float* __restrict__ x) {
    int idx = blockIdx.x * 256 + threadIdx.x;      // 0 .. B*N-1
    int b = idx >> 13;
    int n = idx & (N_ - 1);
    const float* xb = x + (size_t)b * C_ * N_ + n;
    float v[C_];
    float acc = 0.f;
#pragma unroll
    for (int c = 0; c < C_; ++c) {
        float t = xb[(size_t)c * N_];              // coalesced across threads
        v[c] = t;
        acc = fmaf(t, t, acc);
    }
    float4* fp = reinterpret_cast<float4*>(g_feats + (size_t)idx * C_);
#pragma unroll
    for (int i = 0; i < C_ / 4; ++i)
        fp[i] = make_float4(v[4 * i], v[4 * i + 1], v[4 * i + 2], v[4 * i + 3]);

    unsigned pk[16];
    int xxq = 0;
#pragma unroll
    for (int g = 0; g < 16; ++g) {
        unsigned p = 0;
#pragma unroll
        for (int e = 0; e < 4; ++e) {
            float s = fminf(fmaxf(v[4 * g + e] * QS, -127.f), 127.f);
            int qi = __float2int_rn(s);
            xxq += qi * qi;
            p |= ((unsigned)qi & 0xFFu) << (8 * e);
        }
        pk[g] = p;
    }
    uint4* qp = reinterpret_cast<uint4*>(g_q8 + (size_t)idx * 16);
#pragma unroll
    for (int i = 0; i < 4; ++i)
        qp[i] = make_uint4(pk[4 * i], pk[4 * i + 1], pk[4 * i + 2], pk[4 * i + 3]);

    g_xxq[idx] = xxq;
    g_xx[idx] = acc;
}

// ---------------- kernel 2: imma KNN filter + exact fp32 rescore ----------------
// Grid (N/128, B_) = 256 CTAs, 256 threads, occ 2. CTA: 128 queries x all 8192 cands.
// smem layout (bytes):
#define S_A    0                          // A int8 tile 128x64 = 8192
#define S_B    8192                       // 2 x 4096 cand tiles
#define S_CXQ  16384                      // 2 x 64 ints
#define S_DIST 16896                      // 128 x 66 ints = 33792
#define S_FD   50688                      // F_ x 256 ints
#define S_FI   62976                      // F_ x 256 ints
#define KNN_SMEM 75264

__global__ void __launch_bounds__(256, 2) knn_kernel() {
    extern __shared__ char smem[];
    uint32_t sb = smem_u32(smem);
    const int t = threadIdx.x;
    const int w = t >> 5;
    const int l = t & 31;
    const int gid = l >> 2;                // 0..7
    const int tig = l & 3;                 // 0..3
    const int b = blockIdx.y;
    const int q0 = blockIdx.x * 128;

    const int m0 = (w & 3) * 32;           // warp query-row base
    const int n0 = (w >> 2) * 32;          // warp cand-col base

    const unsigned* q8b = g_q8 + (size_t)b * N_ * 16;
    const int* xxqb = g_xxq + b * N_;

    int* s_cxq = reinterpret_cast<int*>(smem + S_CXQ);
    int* s_fd  = reinterpret_cast<int*>(smem + S_FD);
    int* s_fi  = reinterpret_cast<int*>(smem + S_FI);
    const uint32_t fd = sb + S_FD + t * 4;
    const uint32_t fi = sb + S_FI + t * 4;

    // ---- A tile load (once): 128 rows x 64B = 512 chunks ----
    {
        const char* asrc = reinterpret_cast<const char*>(q8b + (size_t)q0 * 16);
        cp_async16(sb + S_A + (uint32_t)t * 16, asrc + (size_t)t * 16);
        cp_async16(sb + S_A + (uint32_t)(t + 256) * 16, asrc + (size_t)(t + 256) * 16);
    }
    // ---- B tile loader: 64 rows x 64B = 256 chunks, 1 per thread ----
    auto issueB = [&](int tile, int buf) {
        const char* src = reinterpret_cast<const char*>(q8b + (size_t)(tile * NTILE) * 16);
        cp_async16(sb + S_B + buf * 4096 + (uint32_t)t * 16, src + (size_t)t * 16);
        cp_commit();
        if (t < NTILE) s_cxq[buf * NTILE + t] = xxqb[tile * NTILE + t];
    };
    issueB(0, 0);

    // per-thread query norms: rows m0 + mf*16 + gid (+8)
    int qn[4];
#pragma unroll
    for (int mf = 0; mf < 2; ++mf) {
        qn[mf * 2] = xxqb[q0 + m0 + mf * 16 + gid];
        qn[mf * 2 + 1] = xxqb[q0 + m0 + mf * 16 + gid + 8];
    }

    int mv[M_KEEP], mi[M_KEEP];
#pragma unroll
    for (int i = 0; i < M_KEEP; ++i) { mv[i] = (int)0x80000000; mi[i] = 0; }
    int thr = (int)0x80000000;
    int cnt = 0;

    cp_wait0();
    __syncthreads();                        // A + B[0] + cxq[0] visible

    // ---- persistent A fragments: af[mf][ks][4] ----
    unsigned af[2][2][4];
#pragma unroll
    for (int mf = 0; mf < 2; ++mf)
#pragma unroll
        for (int ks = 0; ks < 2; ++ks) {
            const char* ab = smem + S_A + (m0 + mf * 16 + gid) * 64 + ks * 32 + tig * 4;
            af[mf][ks][0] = *reinterpret_cast<const unsigned*>(ab);
            af[mf][ks][1] = *reinterpret_cast<const unsigned*>(ab + 512);   // row +8
            af[mf][ks][2] = *reinterpret_cast<const unsigned*>(ab + 16);    // k +16
            af[mf][ks][3] = *reinterpret_cast<const unsigned*>(ab + 512 + 16);
        }

    const int srow = t & 127;               // scan: query row
    const int shalf = t >> 7;               // scan: column half (32 cols)
    int* dist = reinterpret_cast<int*>(smem + S_DIST);

    for (int tile = 0; tile < NT2; ++tile) {
        const int buf = tile & 1;
        if (tile + 1 < NT2) { issueB(tile + 1, buf ^ 1); cp_wait1(); }
        else                { cp_wait0(); }
        __syncthreads();                    // B(tile)+cxq ready; prev scan done (dist free)

        // ---- MMA: 2mf x 4nf x 2ks = 16 imma ----
        const char* Bt = smem + S_B + buf * 4096;
        int acc[2][4][4];
#pragma unroll
        for (int mf = 0; mf < 2; ++mf)
#pragma unroll
            for (int nf = 0; nf < 4; ++nf)
#pragma unroll
                for (int r = 0; r < 4; ++r) acc[mf][nf][r] = 0;

#pragma unroll
        for (int ks = 0; ks < 2; ++ks) {
            unsigned bf[4][2];
#pragma unroll
            for (int nf = 0; nf < 4; ++nf) {
                const char* bb = Bt + (n0 + nf * 8 + gid) * 64 + ks * 32 + tig * 4;
                bf[nf][0] = *reinterpret_cast<const unsigned*>(bb);
                bf[nf][1] = *reinterpret_cast<const unsigned*>(bb + 16);
            }
#pragma unroll
            for (int mf = 0; mf < 2; ++mf)
#pragma unroll
                for (int nf = 0; nf < 4; ++nf)
                    imma(acc[mf][nf], af[mf][ks], bf[nf]);
        }

        // ---- fold: d = 2*acc - qxx - cxx -> dist tile (stride 66 ints) ----
#pragma unroll
        for (int nf = 0; nf < 4; ++nf) {
            int col = n0 + nf * 8 + tig * 2;
            int2 cx2 = *reinterpret_cast<const int2*>(s_cxq + buf * NTILE + col);
#pragma unroll
            for (int mf = 0; mf < 2; ++mf) {
                int row = m0 + mf * 16 + gid;
                int2 dlo, dhi;
                dlo.x = (acc[mf][nf][0] << 1) - qn[mf * 2] - cx2.x;
                dlo.y = (acc[mf][nf][1] << 1) - qn[mf * 2] - cx2.y;
                dhi.x = (acc[mf][nf][2] << 1) - qn[mf * 2 + 1] - cx2.x;
                dhi.y = (acc[mf][nf][3] << 1) - qn[mf * 2 + 1] - cx2.y;
                *reinterpret_cast<int2*>(dist + row * 66 + col) = dlo;
                *reinterpret_cast<int2*>(dist + (row + 8) * 66 + col) = dhi;
            }
        }
        __syncthreads();                    // dist complete

        // ---- scan: thread owns (srow, 32-col half); dmax guard per 8-batch ----
        {
            const int2* base2 = reinterpret_cast<const int2*>(dist + srow * 66 + shalf * 32);
            const int cbase = tile * NTILE + shalf * 32;
#pragma unroll 1
            for (int jb = 0; jb < 4; ++jb) {
                int2 v0 = base2[jb * 4 + 0];
                int2 v1 = base2[jb * 4 + 1];
                int2 v2 = base2[jb * 4 + 2];
                int2 v3 = base2[jb * 4 + 3];
                int d[8] = { v0.x, v0.y, v1.x, v1.y, v2.x, v2.y, v3.x, v3.y };
                int dmax = d[0];
#pragma unroll
                for (int e = 1; e < 8; ++e) dmax = max(dmax, d[e]);
                if (dmax > thr) {           // rare after warm-up (R11-proven guard)
#pragma unroll
                    for (int e = 0; e < 8; ++e) {
                        fifo_push(fd, fi, cnt, d[e], cbase + jb * 8 + e, thr);
                        cnt += (d[e] > thr) ? 1 : 0;
                    }
                }
                // uniform-mask flush check (outside the divergent guard)
                if (__any_sync(0xffffffffu, cnt > F_ - 8)) {
                    int m = (int)__reduce_max_sync(0xffffffffu, (unsigned)cnt);
#pragma unroll 1
                    for (int e = 0; e < m; ++e)
                        insM(mv, mi, s_fd[e * 256 + t], s_fi[e * 256 + t], e < cnt);
                    thr = mv[M_KEEP - 1];
                    cnt = 0;
                }
            }
        }
        // loop-top __syncthreads separates this scan from next fold
    }

    // final flush
    {
        int m = (int)__reduce_max_sync(0xffffffffu, (unsigned)cnt);
#pragma unroll 1
        for (int e = 0; e < m; ++e)
            insM(mv, mi, s_fd[e * 256 + t], s_fi[e * 256 + t], e < cnt);
    }

    // ---- exact fp32 rescore (proven path) ----
    const int q = q0 + srow;
    float fv[M_KEEP];
    {
        const float* fbf = g_feats + (size_t)b * N_ * C_;
        const float* xxb = g_xx + b * N_;
        const u64* qp = reinterpret_cast<const u64*>(fbf + (size_t)q * C_);
        u64 qv2[32];
#pragma unroll
        for (int i = 0; i < 32; ++i) qv2[i] = qp[i];
        float qxxe = xxb[q];
#pragma unroll
        for (int i = 0; i < M_KEEP; ++i) {
            int idx = mi[i];
            const u64* cp = reinterpret_cast<const u64*>(fbf + (size_t)idx * C_);
            u64 a0 = 0, a1 = 0, a2 = 0, a3 = 0;
#pragma unroll
            for (int j = 0; j < 8; ++j) {
                a0 = fma2(qv2[4 * j + 0], cp[4 * j + 0], a0);
                a1 = fma2(qv2[4 * j + 1], cp[4 * j + 1], a1);
                a2 = fma2(qv2[4 * j + 2], cp[4 * j + 2], a2);
                a3 = fma2(qv2[4 * j + 3], cp[4 * j + 3], a3);
            }
            float inner = psum(add2(add2(a0, a1), add2(a2, a3)));
            fv[i] = 2.f * inner - qxxe - xxb[idx];
        }
    }

    // odd-even sort by (val desc, idx asc)
#pragma unroll
    for (int pass = 0; pass < M_KEEP; ++pass) {
#pragma unroll
        for (int i = (pass & 1); i + 1 < M_KEEP; i += 2) {
            bool sw = (fv[i + 1] > fv[i]) || (fv[i + 1] == fv[i] && mi[i + 1] < mi[i]);
            float tv = sw ? fv[i + 1] : fv[i];
            fv[i + 1] = sw ? fv[i] : fv[i + 1];
            fv[i] = tv;
            int ti = sw ? mi[i + 1] : mi[i];
            mi[i + 1] = sw ? mi[i] : mi[i + 1];
            mi[i] = ti;
        }
    }

    // write partial list (list id = b*NL + shalf)
    {
        size_t L = (size_t)(b * NL + shalf);
        float* pv = g_pval + (L * N_ + q) * M_KEEP;
        int*   pi = g_pidx + (L * N_ + q) * M_KEEP;
#pragma unroll
        for (int i = 0; i < M_KEEP; ++i) { pv[i] = fv[i]; pi[i] = mi[i]; }
    }
}

// ---------------- kernel 2b: NL-way merge of partial top lists ----------------
__global__ void __launch_bounds__(256) merge_kernel() {
    int id = blockIdx.x * 256 + threadIdx.x;       // 0 .. B*N-1
    int b = id >> 13;
    int q = id & (N_ - 1);

    const float* pv[NL];
    const int*   pi[NL];
    float hv[NL];
    int   hx[NL];
    int   cur[NL];
#pragma unroll
    for (int c = 0; c < NL; ++c) {
        pv[c] = g_pval + (((size_t)(b * NL + c)) * N_ + q) * M_KEEP;
        pi[c] = g_pidx + (((size_t)(b * NL + c)) * N_ + q) * M_KEEP;
        hv[c] = pv[c][0];
        hx[c] = pi[c][0];
        cur[c] = 0;
    }
    int* og = g_knn + (size_t)id * K_;
#pragma unroll
    for (int s = 0; s < 16; ++s) {
        int best = 0;
#pragma unroll
        for (int c = 1; c < NL; ++c)
            if (hv[c] > hv[best] || (hv[c] == hv[best] && hx[c] < hx[best])) best = c;
        og[s] = hx[best];
        if (++cur[best] < M_KEEP) {
            hv[best] = pv[best][cur[best]];
            hx[best] = pi[best][cur[best]];
        } else {
            hv[best] = -3.4e38f;
            hx[best] = 0x7fffffff;
        }
    }
}

// ---------------- kernel 3a: per-point GEMM  Y = W2.x, Z = (W1-W2).x ----------------
__global__ void __launch_bounds__(128) zy_kernel(const float* __restrict__ W) {
    __shared__ __align__(16) float s_x[64 * C_];    // 16 KB point tile
    const int t = threadIdx.x;                      // channel
    const int b = blockIdx.y;
    const int p0 = blockIdx.x * 64;

    {
        uint32_t dst = smem_u32(s_x);
        const char* src = reinterpret_cast<const char*>(g_feats + ((size_t)b * N_ + p0) * C_);
#pragma unroll
        for (int i = 0; i < 8; ++i) {
            int c = t + i * 128;
            cp_async16(dst + (uint32_t)c * 16, src + (size_t)c * 16);
        }
        cp_commit();
    }

    u64 w2r[32], wzr[32];
    {
        const u64* wp = reinterpret_cast<const u64*>(W + (size_t)t * 2 * C_);
        const u64 neg1 = dup2(-1.f);
#pragma unroll
        for (int i = 0; i < 32; ++i) {
            u64 w1 = wp[i];
            u64 w2 = wp[32 + i];
            w2r[i] = w2;
            wzr[i] = fma2(w2, neg1, w1);            // w1 - w2 (exact)
        }
    }

    float* Yb = g_Y + ((size_t)b * N_ + p0) * O_;
    float* Zb = g_Z + ((size_t)b * N_ + p0) * O_;

    cp_wait0();
    __syncthreads();

#pragma unroll 1
    for (int pl = 0; pl < 64; ++pl) {
        const ulonglong2* xp = reinterpret_cast<const ulonglong2*>(s_x + pl * C_);
        u64 y0 = 0, y1 = 0, y2 = 0, y3 = 0;
        u64 z0 = 0, z1 = 0, z2 = 0, z3 = 0;
#pragma unroll
        for (int i = 0; i < 8; ++i) {
            ulonglong2 ua = xp[2 * i];
            ulonglong2 ub = xp[2 * i + 1];
            y0 = fma2(w2r[4 * i + 0], ua.x, y0);
            y1 = fma2(w2r[4 * i + 1], ua.y, y1);
            y2 = fma2(w2r[4 * i + 2], ub.x, y2);
            y3 = fma2(w2r[4 * i + 3], ub.y, y3);
            z0 = fma2(wzr[4 * i + 0], ua.x, z0);
            z1 = fma2(wzr[4 * i + 1], ua.y, z1);
            z2 = fma2(wzr[4 * i + 2], ub.x, z2);
            z3 = fma2(wzr[4 * i + 3], ub.y, z3);
        }
        Yb[pl * O_ + t] = psum(add2(add2(y0, y1), add2(y2, y3)));
        Zb[pl * O_ + t] = psum(add2(add2(z0, z1), add2(z2, z3)));
    }
}

// ---------------- kernel 3b: gather-max epilogue ----------------
#define GPB 64
__global__ void __launch_bounds__(128) gmax_kernel(const float* __restrict__ bias,
                                                   float* __restrict__ out) {
    __shared__ int   s_nidx[GPB * K_];
    __shared__ float s_res[128 * 65];

    const int t = threadIdx.x;                      // channel
    const int b = blockIdx.y;
    const int p0 = blockIdx.x * GPB;

    const float* Yb = g_Y + (size_t)b * N_ * O_;
    const float* Zb = g_Z + (size_t)b * N_ * O_;
    const float bo = bias[t];

    for (int i = t; i < GPB * K_; i += 128)
        s_nidx[i] = g_knn[(size_t)(b * N_ + p0) * K_ + i];
    __syncthreads();

#pragma unroll 1
    for (int pl = 0; pl < GPB; ++pl) {
        const int* nn = s_nidx + pl * K_;
        float m = -3.4e38f;
#pragma unroll
        for (int k = 0; k < K_; ++k)
            m = fmaxf(m, Yb[(size_t)nn[k] * O_ + t]);
        float z = Zb[(size_t)(p0 + pl) * O_ + t];
        s_res[t * 65 + pl] = z + m + bo;
    }
    __syncthreads();

#pragma unroll
    for (int i = 0; i < 64; ++i) {
        int idx = t + i * 128;
        int o = idx >> 6;
        int p = idx & 63;
        out[((size_t)(b * O_ + o)) * N_ + p0 + p] = s_res[o * 65 + p];
    }
}

// ---------------- launch ----------------
extern "C" void kernel_launch(void* const* d_in, const int* in_sizes, int n_in,
                              void* d_out, int out_size) {
    (void)in_sizes; (void)n_in; (void)out_size;
    const float* x    = (const float*)d_in[0];   // (4, 64, 8192, 1)
    const float* W    = (const float*)d_in[1];   // (128, 128)
    const float* bias = (const float*)d_in[2];   // (128,)
    float* out = (float*)d_out;                  // (4, 128, 8192, 1)

    cudaFuncSetAttribute(knn_kernel, cudaFuncAttributeMaxDynamicSharedMemorySize, KNN_SMEM);

    prep_kernel<<<(B_ * N_) / 256, 256>>>(x);
    knn_kernel<<<dim3(N_ / 128, B_), 256, KNN_SMEM>>>();
    merge_kernel<<<(B_ * N_) / 256, 256>>>();
    zy_kernel<<<dim3(N_ / 64, B_), 128>>>(W);
    gmax_kernel<<<dim3(N_ / GPB, B_), 128>>>(bias, out);
}